// round 10
// baseline (speedup 1.0000x reference)
#include <cuda_runtime.h>
#include <cuda_fp16.h>
#include <cstdint>
#include <math.h>

#define H      2048
#define HH     1024
#define BATCH  4
#define SEQ    4096
#define M_ROWS 16384
#define SUPC   4
#define HEADSC 8

// d_out float offsets (tuple order, flattened)
#define OFF_TOK  0
#define OFF_CTX  16384
#define OFF_TASK 16388
#define OFF_SUP  16392
#define OFF_DEP  81928
#define OFF_EFF  213000
#define OFF_MASK 229384

#define RECHECK_MARGIN 0.005f
#define RE_MAX_ROWS    4096
#define RE_BLOCKS      256       // 32 m-blocks x 8 n-blocks
#define TG             512       // GEMM threads (16 warps, 4/SMSP)

// ================= scratch (no allocations allowed) =================
__device__ float g_ctxsum[BATCH * H];
__device__ float g_rowsum0[M_ROWS];
__device__ float g_rowsum1[M_ROWS];
__device__ float g_slog[M_ROWS * SUPC];
__device__ float g_dlog[M_ROWS * HEADSC];
__device__ int   g_count;
__device__ int   g_rowmap[M_ROWS];
__device__ float g_rlog[M_ROWS * SUPC];

__device__ __half gX0[M_ROWS * H];
__device__ __half gX1[M_ROWS * H];
__device__ __half gWtok0[HH * H];
__device__ __half gWeff0[HH * H];
__device__ __half gWsup0[H * H];
__device__ __half gWsup1[H * H];
__device__ __half gWdep0[H * H];

__device__ __forceinline__ float gelu_exact(float x) {
    return 0.5f * x * (1.0f + erff(x * 0.70710678118654752f));
}
__device__ __forceinline__ float sigmoidf_(float x) {
    return 1.0f / (1.0f + expf(-x));
}
__device__ __forceinline__ uint32_t smem_to_u32(const void* p) {
    uint32_t a;
    asm("{ .reg .u64 t; cvta.to.shared.u64 t, %1; cvt.u32.u64 %0, t; }" : "=r"(a) : "l"(p));
    return a;
}
#define SWZ(off) ((off) ^ (((off) >> 3) & 0x70))

#define LDSM4(r, addr) \
    asm volatile("ldmatrix.sync.aligned.m8n8.x4.shared.b16 {%0,%1,%2,%3}, [%4];" \
                 : "=r"((r)[0]), "=r"((r)[1]), "=r"((r)[2]), "=r"((r)[3]) : "r"(addr))

static constexpr int ASZ_C = 128 * 128;   // 16KB: A tile (128 rows x 64 fp16)
static constexpr int BSZ_C = 256 * 128;   // 32KB: B tile (256 rows x 64 fp16)
static constexpr int STG1  = ASZ_C + BSZ_C;   // 48KB stage
static constexpr int SM1   = 3 * STG1;        // 147456
static constexpr int STG3  = 2 * STG1;        // 96KB (recheck: 2 parts)
static constexpr int SM_CMB = 2 * STG3;       // 196608

// 16-warp mapping: warp grid 4(m) x 4(n), warp tile 32x64, acc[2][8][4]
__device__ __forceinline__ void mmas(float (&acc)[2][8][4],
                                     uint32_t (&a)[2][4], uint32_t (&b)[4][4]) {
    #pragma unroll
    for (int ms = 0; ms < 2; ms++)
        #pragma unroll
        for (int ns = 0; ns < 8; ns++) {
            uint32_t b0 = b[ns >> 1][ns & 1];
            uint32_t b1 = b[ns >> 1][2 + (ns & 1)];
            asm volatile(
                "mma.sync.aligned.m16n8k16.row.col.f32.f16.f16.f32 "
                "{%0,%1,%2,%3}, {%4,%5,%6,%7}, {%8,%9}, {%0,%1,%2,%3};"
                : "+f"(acc[ms][ns][0]), "+f"(acc[ms][ns][1]),
                  "+f"(acc[ms][ns][2]), "+f"(acc[ms][ns][3])
                : "r"(a[ms][0]), "r"(a[ms][1]), "r"(a[ms][2]), "r"(a[ms][3]),
                  "r"(b0), "r"(b1));
        }
}

__device__ __forceinline__ void ldfragA(uint32_t Ab, int wm, int r16, int kb,
                                        uint32_t (&a)[2][4]) {
    #pragma unroll
    for (int ms = 0; ms < 2; ms++)
        LDSM4(a[ms], Ab + SWZ((wm * 32 + ms * 16 + r16) * 128 + kb));
}
__device__ __forceinline__ void ldfragB(uint32_t Bb, int wn, int r16, int kb,
                                        uint32_t (&b)[4][4]) {
    #pragma unroll
    for (int nt = 0; nt < 4; nt++)
        LDSM4(b[nt], Bb + SWZ((wn * 64 + nt * 16 + r16) * 128 + kb));
}

__device__ __forceinline__ void compute_chunk1(uint32_t Ab, uint32_t Bb,
        float (&acc)[2][8][4], int wm, int wn, int lane) {
    const int r16 = lane & 15;
    const int kg  = (lane >> 4) * 16;
    #pragma unroll
    for (int ks = 0; ks < 4; ks++) {
        const int kb = ks * 32 + kg;
        uint32_t a[2][4], b[4][4];
        ldfragA(Ab, wm, r16, kb, a);
        ldfragB(Bb, wn, r16, kb, b);
        mmas(acc, a, b);
    }
}

// ---- loaders (tid strides over TG threads) ----
__device__ __forceinline__ void load1(uint32_t dstbase, int kc, int m0, int n0,
                                      int tid, const __half* __restrict__ A0,
                                      const __half* __restrict__ B0) {
    for (int idx = tid; idx < 3072; idx += TG) {
        uint32_t dst;
        const __half* src;
        if (idx < 1024) {
            int r = idx >> 3, i = idx & 7;
            dst = dstbase + SWZ(r * 128 + i * 16);
            src = A0 + (size_t)(m0 + r) * H + kc * 64 + i * 8;
        } else {
            int j = idx - 1024;
            int r = j >> 3, i = j & 7;
            dst = dstbase + ASZ_C + SWZ(r * 128 + i * 16);
            src = B0 + (size_t)(n0 + r) * H + kc * 64 + i * 8;
        }
        asm volatile("cp.async.cg.shared.global [%0], [%1], 16;" :: "r"(dst), "l"(src) : "memory");
    }
    asm volatile("cp.async.commit_group;" ::: "memory");
}

__device__ __forceinline__ void load3(uint32_t dstbase, int kc, int tid,
                                      const int* rs, int n0,
                                      const __half* __restrict__ A0,
                                      const __half* __restrict__ A1,
                                      const __half* __restrict__ B0,
                                      const __half* __restrict__ B1) {
    for (int idx = tid; idx < 2048 + 4096; idx += TG) {
        uint32_t dst;
        const __half* src;
        if (idx < 2048) {
            int s = idx >> 10;
            int r = (idx & 1023) >> 3;
            int i = idx & 7;
            dst = dstbase + s * ASZ_C + SWZ(r * 128 + i * 16);
            src = (s ? A1 : A0) + (size_t)rs[r] * H + kc * 64 + i * 8;
        } else {
            int j = idx - 2048;
            int s = j >> 11;
            int r = (j & 2047) >> 3;
            int i = j & 7;
            dst = dstbase + 2 * ASZ_C + s * BSZ_C + SWZ(r * 128 + i * 16);
            src = (s ? B1 : B0) + (size_t)(n0 + r) * H + kc * 64 + i * 8;
        }
        asm volatile("cp.async.cg.shared.global [%0], [%1], 16;" :: "r"(dst), "l"(src) : "memory");
    }
    asm volatile("cp.async.commit_group;" ::: "memory");
}

// ---- single-pass GEMM body (compile-time C/EX), 512 threads ----
template <int C, bool EX>
__device__ __forceinline__ void gemm1_body(
    uint32_t base, int m0, int n0, int tid,
    const __half* __restrict__ A0, const __half* __restrict__ B0,
    const float* __restrict__ bias1, const float* __restrict__ W2,
    const float* __restrict__ W1o, float* __restrict__ accout,
    const float* __restrict__ tcv, const float* __restrict__ ccv,
    const float* __restrict__ tkv, int Ntot)
{
    constexpr int NC = H / 64;
    const int lane = tid & 31;
    const int wid  = tid >> 5;    // 0..15
    const int wm   = wid >> 2;    // 0..3 (32 rows each)
    const int wn   = wid & 3;     // 0..3 (64 cols each)

    float acc[2][8][4];
    #pragma unroll
    for (int a = 0; a < 2; a++)
        #pragma unroll
        for (int b = 0; b < 8; b++)
            #pragma unroll
            for (int c = 0; c < 4; c++) acc[a][b][c] = 0.f;

    load1(base + 0 * STG1, 0, m0, n0, tid, A0, B0);
    load1(base + 1 * STG1, 1, m0, n0, tid, A0, B0);

    for (int c = 0; c < NC; c++) {
        if (c + 2 < NC)
            load1(base + ((c + 2) % 3) * STG1, c + 2, m0, n0, tid, A0, B0);
        if (c + 2 < NC)      asm volatile("cp.async.wait_group %0;" :: "n"(2) : "memory");
        else if (c + 1 < NC) asm volatile("cp.async.wait_group %0;" :: "n"(1) : "memory");
        else                 asm volatile("cp.async.wait_group %0;" :: "n"(0) : "memory");
        __syncthreads();
        const uint32_t sb = base + (c % 3) * STG1;
        compute_chunk1(sb, sb + ASZ_C, acc, wm, wn, lane);
        __syncthreads();
    }

    float ccs = 0.f, tks = 0.f;
    if (EX) { ccs = ccv[m0 >> 12]; tks = tkv[m0 >> 12]; }

    #pragma unroll
    for (int ms = 0; ms < 2; ms++) {
        #pragma unroll
        for (int hh = 0; hh < 2; hh++) {
            const int r = m0 + wm * 32 + ms * 16 + (lane >> 2) + hh * 8;
            float tc = 0.f;
            if (EX) tc = tcv[r];
            float pc[C];
            #pragma unroll
            for (int ci = 0; ci < C; ci++) pc[ci] = 0.f;
            #pragma unroll
            for (int ns = 0; ns < 8; ns++) {
                #pragma unroll
                for (int e = 0; e < 2; e++) {
                    const int n = n0 + wn * 64 + ns * 8 + (lane & 3) * 2 + e;
                    float v = acc[ms][ns][hh * 2 + e] + bias1[n];
                    if (EX) {
                        v += tc  * W1o[(size_t)2048 * Ntot + n]
                           + ccs * W1o[(size_t)2049 * Ntot + n]
                           + tks * W1o[(size_t)2050 * Ntot + n];
                    }
                    float h = gelu_exact(v);
                    #pragma unroll
                    for (int ci = 0; ci < C; ci++)
                        pc[ci] = fmaf(h, W2[(size_t)n * C + ci], pc[ci]);
                }
            }
            #pragma unroll
            for (int ci = 0; ci < C; ci++) {
                pc[ci] += __shfl_xor_sync(0xffffffffu, pc[ci], 1);
                pc[ci] += __shfl_xor_sync(0xffffffffu, pc[ci], 2);
            }
            if ((lane & 3) == 0) {
                #pragma unroll
                for (int ci = 0; ci < C; ci++)
                    atomicAdd(&accout[(size_t)r * C + ci], pc[ci]);
            }
        }
    }
}

template <int C, bool EX>
__global__ void __launch_bounds__(TG, 1)
tc_gemm1(const __half* __restrict__ A0, const __half* __restrict__ B0,
         const float* __restrict__ bias1, const float* __restrict__ W2,
         const float* __restrict__ W1o, float* __restrict__ accout,
         const float* __restrict__ tcv, const float* __restrict__ ccv,
         const float* __restrict__ tkv, int Ntot)
{
    extern __shared__ char smem[];
    gemm1_body<C, EX>(smem_to_u32(smem), blockIdx.y * 128, blockIdx.x * 256,
                      threadIdx.x, A0, B0, bias1, W2, W1o, accout, tcv, ccv, tkv, Ntot);
}

// ---- gathered 3-term recheck body (512 threads) ----
__device__ __forceinline__ void recheck_body(
    uint32_t base, int m0, int n0, int tid, int* rowsm,
    const __half* __restrict__ A0, const __half* __restrict__ A1,
    const __half* __restrict__ B0, const __half* __restrict__ B1,
    const float* __restrict__ bias1, const float* __restrict__ W2,
    const float* __restrict__ W1o, float* __restrict__ accout,
    const float* __restrict__ tcv, const float* __restrict__ ccv,
    const float* __restrict__ tkv)
{
    constexpr int NC = H / 64;
    const int lane = tid & 31;
    const int wid  = tid >> 5;
    const int wm   = wid >> 2;
    const int wn   = wid & 3;

    for (int i = tid; i < 128; i += TG) rowsm[i] = g_rowmap[m0 + i];
    __syncthreads();

    float acc[2][8][4];
    #pragma unroll
    for (int a = 0; a < 2; a++)
        #pragma unroll
        for (int b = 0; b < 8; b++)
            #pragma unroll
            for (int c = 0; c < 4; c++) acc[a][b][c] = 0.f;

    load3(base, 0, tid, rowsm, n0, A0, A1, B0, B1);

    for (int c = 0; c < NC; c++) {
        if (c + 1 < NC)
            load3(base + ((c + 1) & 1) * STG3, c + 1, tid, rowsm, n0, A0, A1, B0, B1);
        if (c + 1 < NC) asm volatile("cp.async.wait_group %0;" :: "n"(1) : "memory");
        else            asm volatile("cp.async.wait_group %0;" :: "n"(0) : "memory");
        __syncthreads();
        const uint32_t sb = base + (c & 1) * STG3;
        const uint32_t Ab = sb, Bb = sb + 2 * ASZ_C;
        {
            const int r16 = lane & 15;
            const int kg  = (lane >> 4) * 16;
            #pragma unroll
            for (int ks = 0; ks < 4; ks++) {
                const int kb = ks * 32 + kg;
                uint32_t af0[2][4], bf0[4][4];
                ldfragA(Ab, wm, r16, kb, af0);
                ldfragB(Bb, wn, r16, kb, bf0);
                mmas(acc, af0, bf0);
                uint32_t af1[2][4];
                ldfragA(Ab + ASZ_C, wm, r16, kb, af1);
                mmas(acc, af1, bf0);
                uint32_t bf1[4][4];
                ldfragB(Bb + BSZ_C, wn, r16, kb, bf1);
                mmas(acc, af0, bf1);
            }
        }
        __syncthreads();
    }

    #pragma unroll
    for (int ms = 0; ms < 2; ms++) {
        #pragma unroll
        for (int hh = 0; hh < 2; hh++) {
            const int slot = m0 + wm * 32 + ms * 16 + (lane >> 2) + hh * 8;
            const int rg   = rowsm[slot - m0];
            float tc = tcv[rg], ccs = ccv[rg >> 12], tks = tkv[rg >> 12];
            float pc[SUPC];
            #pragma unroll
            for (int ci = 0; ci < SUPC; ci++) pc[ci] = 0.f;
            #pragma unroll
            for (int ns = 0; ns < 8; ns++) {
                #pragma unroll
                for (int e = 0; e < 2; e++) {
                    const int n = n0 + wn * 64 + ns * 8 + (lane & 3) * 2 + e;
                    float v = acc[ms][ns][hh * 2 + e] + bias1[n];
                    v += tc  * W1o[(size_t)2048 * H + n]
                       + ccs * W1o[(size_t)2049 * H + n]
                       + tks * W1o[(size_t)2050 * H + n];
                    float h = gelu_exact(v);
                    #pragma unroll
                    for (int ci = 0; ci < SUPC; ci++)
                        pc[ci] = fmaf(h, W2[(size_t)n * SUPC + ci], pc[ci]);
                }
            }
            #pragma unroll
            for (int ci = 0; ci < SUPC; ci++) {
                pc[ci] += __shfl_xor_sync(0xffffffffu, pc[ci], 1);
                pc[ci] += __shfl_xor_sync(0xffffffffu, pc[ci], 2);
            }
            if ((lane & 3) == 0) {
                #pragma unroll
                for (int ci = 0; ci < SUPC; ci++)
                    atomicAdd(&accout[(size_t)slot * SUPC + ci], pc[ci]);
            }
        }
    }
}

// ---- combined dep GEMM + recheck (single launch -> overlap) ----
__global__ void __launch_bounds__(TG, 1)
tc_gemm_dep_re(const __half* __restrict__ X0, const __half* __restrict__ X1,
               const __half* __restrict__ Wd0,
               const __half* __restrict__ Ws0, const __half* __restrict__ Ws1,
               const float* __restrict__ depb1, const float* __restrict__ depW2,
               const float* __restrict__ depW1,
               const float* __restrict__ supb1, const float* __restrict__ supW2,
               const float* __restrict__ supW1,
               float* __restrict__ dlog, float* __restrict__ rlog,
               const float* __restrict__ tcv, const float* __restrict__ ccv,
               const float* __restrict__ tkv)
{
    extern __shared__ char smem[];
    __shared__ int rowsm[128];
    const uint32_t base = smem_to_u32(smem);
    const int bid = blockIdx.x;
    const int tid = threadIdx.x;

    if (bid < RE_BLOCKS) {
        const int m0 = (bid >> 3) * 128;
        const int n0 = (bid & 7) * 256;
        if (m0 >= g_count) return;
        recheck_body(base, m0, n0, tid, rowsm, X0, X1, Ws0, Ws1,
                     supb1, supW2, supW1, rlog, tcv, ccv, tkv);
    } else {
        const int b2 = bid - RE_BLOCKS;
        const int m0 = (b2 >> 3) * 128;
        const int n0 = (b2 & 7) * 256;
        gemm1_body<HEADSC, true>(base, m0, n0, tid, X0, Wd0,
                                 depb1, depW2, depW1, dlog, tcv, ccv, tkv, H);
    }
}

// ================= precompute kernels =================
__global__ void split_x_mean(const float* __restrict__ X) {
    int idx = blockIdx.x * blockDim.x + threadIdx.x;
    int d     = idx & (H - 1);
    int chunk = (idx >> 11) & 15;
    int b     = idx >> 15;
    size_t p = ((size_t)(b * SEQ + chunk * 256)) * H + d;
    float s = 0.f;
    #pragma unroll 4
    for (int t = 0; t < 256; t++) {
        float x = X[p];
        s += x;
        __half h = __float2half_rn(x);
        gX0[p] = h;
        gX1[p] = __float2half_rn(x - __half2float(h));
        p += H;
    }
    atomicAdd(&g_ctxsum[b * H + d], s);
}

__global__ void transpose_split_w(const float* __restrict__ W, int N, int nsplit,
                                  __half* __restrict__ o0, __half* __restrict__ o1) {
    __shared__ float t[32][33];
    int n0 = blockIdx.x * 32, k0 = blockIdx.y * 32;
    int tx = threadIdx.x & 31, ty = threadIdx.x >> 5;
    #pragma unroll
    for (int s = 0; s < 32; s += 8)
        t[ty + s][tx] = W[(size_t)(k0 + ty + s) * N + n0 + tx];
    __syncthreads();
    #pragma unroll
    for (int s = 0; s < 32; s += 8) {
        int n = n0 + ty + s, k = k0 + tx;
        float x = t[tx][ty + s];
        __half hh = __float2half_rn(x);
        o0[(size_t)n * H + k] = hh;
        if (nsplit == 2) {
            float r = x - __half2float(hh);
            o1[(size_t)n * H + k] = __float2half_rn(r);
        }
    }
}

__global__ void zero_scratch() {
    int i = blockIdx.x * blockDim.x + threadIdx.x;
    if (i == 0)               g_count = 0;
    if (i < BATCH * H)        g_ctxsum[i] = 0.f;
    if (i < M_ROWS)         { g_rowsum0[i] = 0.f; g_rowsum1[i] = 0.f; g_rowmap[i] = 0; }
    if (i < M_ROWS * SUPC)  { g_slog[i] = 0.f; g_rlog[i] = 0.f; }
    if (i < M_ROWS * HEADSC)  g_dlog[i] = 0.f;
}

__global__ void ctx_task_kernel(
    const float* __restrict__ cW1, const float* __restrict__ cb1,
    const float* __restrict__ cW2, const float* __restrict__ cb2,
    const float* __restrict__ tW1, const float* __restrict__ tb1,
    const float* __restrict__ tW2, const float* __restrict__ tb2,
    float* __restrict__ out)
{
    __shared__ float emb[H];
    __shared__ float red[1024];
    int b = blockIdx.x, which = blockIdx.y;
    const float* W1 = which ? tW1 : cW1;
    const float* b1 = which ? tb1 : cb1;
    const float* W2 = which ? tW2 : cW2;
    const float* b2 = which ? tb2 : cb2;
    int tid = threadIdx.x;
    for (int i = tid; i < H; i += 1024)
        emb[i] = g_ctxsum[b * H + i] * (1.0f / SEQ);
    __syncthreads();

    float a = b1[tid];
    #pragma unroll 4
    for (int k = 0; k < H; k++)
        a = fmaf(emb[k], W1[(size_t)k * HH + tid], a);
    red[tid] = gelu_exact(a) * W2[tid];
    __syncthreads();
    for (int off = 512; off > 0; off >>= 1) {
        if (tid < off) red[tid] += red[tid + off];
        __syncthreads();
    }
    if (tid == 0)
        out[(which ? OFF_TASK : OFF_CTX) + b] = sigmoidf_(red[0] + b2[0]);
}

// ================= small finalize kernels =================
__global__ void finalize_tokeff(float* __restrict__ out,
                                const float* __restrict__ tokb2,
                                const float* __restrict__ effb2)
{
    int r = blockIdx.x * blockDim.x + threadIdx.x;
    if (r < M_ROWS) {
        out[OFF_TOK + r] = sigmoidf_(g_rowsum0[r] + tokb2[0]);
        out[OFF_EFF + r] = sigmoidf_(g_rowsum1[r] + effb2[0]);
    }
}

__global__ void softmax_sup_flag(float* __restrict__ out,
                                 const float* __restrict__ supb2)
{
    int r = blockIdx.x * blockDim.x + threadIdx.x;
    if (r >= M_ROWS) return;
    float l[SUPC];
    float m = -1e30f;
    #pragma unroll
    for (int c = 0; c < SUPC; c++) {
        l[c] = g_slog[(size_t)r * SUPC + c] + supb2[c];
        m = fmaxf(m, l[c]);
    }
    float s = 0.f;
    #pragma unroll
    for (int c = 0; c < SUPC; c++) { l[c] = expf(l[c] - m); s += l[c]; }
    float inv = 1.f / s;
    float eff = out[OFF_EFF + r];
    bool flag = false;
    #pragma unroll
    for (int c = 0; c < SUPC; c++) {
        float w = l[c] * inv;
        if (fabsf(w - 0.2f) < RECHECK_MARGIN) flag = true;
        out[OFF_SUP  + (size_t)r * SUPC + c] = w;
        out[OFF_MASK + (size_t)r * SUPC + c] = (w > 0.2f) ? eff : 0.f;
    }
    if (flag) {
        int slot = atomicAdd(&g_count, 1);
        if (slot < M_ROWS) g_rowmap[slot] = r;
    }
}

__global__ void softmax_dep_refinal(float* __restrict__ out,
                                    const float* __restrict__ depb2,
                                    const float* __restrict__ supb2)
{
    int r = blockIdx.x * blockDim.x + threadIdx.x;
    if (r >= M_ROWS) return;
    {
        float l[HEADSC];
        float m = -1e30f;
        #pragma unroll
        for (int c = 0; c < HEADSC; c++) {
            l[c] = g_dlog[(size_t)r * HEADSC + c] + depb2[c];
            m = fmaxf(m, l[c]);
        }
        float s = 0.f;
        #pragma unroll
        for (int c = 0; c < HEADSC; c++) { l[c] = expf(l[c] - m); s += l[c]; }
        float inv = 1.f / s;
        #pragma unroll
        for (int c = 0; c < HEADSC; c++)
            out[OFF_DEP + (size_t)r * HEADSC + c] = l[c] * inv;
    }
    int t = r;
    if (t < g_count && t < RE_MAX_ROWS) {
        int rr = g_rowmap[t];
        float l[SUPC];
        float m = -1e30f;
        #pragma unroll
        for (int c = 0; c < SUPC; c++) {
            l[c] = g_rlog[(size_t)t * SUPC + c] + supb2[c];
            m = fmaxf(m, l[c]);
        }
        float s = 0.f;
        #pragma unroll
        for (int c = 0; c < SUPC; c++) { l[c] = expf(l[c] - m); s += l[c]; }
        float inv = 1.f / s;
        float eff = out[OFF_EFF + rr];
        #pragma unroll
        for (int c = 0; c < SUPC; c++) {
            float w = l[c] * inv;
            out[OFF_SUP  + (size_t)rr * SUPC + c] = w;
            out[OFF_MASK + (size_t)rr * SUPC + c] = (w > 0.2f) ? eff : 0.f;
        }
    }
}

// ================= launch =================
extern "C" void kernel_launch(void* const* d_in, const int* in_sizes, int n_in,
                              void* d_out, int out_size)
{
    const float* X      = (const float*)d_in[0];
    const float* tokW1  = (const float*)d_in[1];
    const float* tokb1  = (const float*)d_in[2];
    const float* tokW2  = (const float*)d_in[3];
    const float* tokb2  = (const float*)d_in[4];
    const float* ctxW1  = (const float*)d_in[5];
    const float* ctxb1  = (const float*)d_in[6];
    const float* ctxW2  = (const float*)d_in[7];
    const float* ctxb2  = (const float*)d_in[8];
    const float* taskW1 = (const float*)d_in[9];
    const float* taskb1 = (const float*)d_in[10];
    const float* taskW2 = (const float*)d_in[11];
    const float* taskb2 = (const float*)d_in[12];
    const float* effW1  = (const float*)d_in[13];
    const float* effb1  = (const float*)d_in[14];
    const float* effW2  = (const float*)d_in[15];
    const float* effb2  = (const float*)d_in[16];
    const float* supW1  = (const float*)d_in[17];
    const float* supb1  = (const float*)d_in[18];
    const float* supW2  = (const float*)d_in[19];
    const float* supb2  = (const float*)d_in[20];
    const float* depW1  = (const float*)d_in[21];
    const float* depb1  = (const float*)d_in[22];
    const float* depW2  = (const float*)d_in[23];
    const float* depb2  = (const float*)d_in[24];
    float* out = (float*)d_out;

    void *pX0, *pX1, *pWt0, *pWe0, *pWs0, *pWs1, *pWd0;
    void *pR0, *pR1, *pSL, *pDL, *pRL;
    cudaGetSymbolAddress(&pX0, gX0);   cudaGetSymbolAddress(&pX1, gX1);
    cudaGetSymbolAddress(&pWt0, gWtok0);
    cudaGetSymbolAddress(&pWe0, gWeff0);
    cudaGetSymbolAddress(&pWs0, gWsup0); cudaGetSymbolAddress(&pWs1, gWsup1);
    cudaGetSymbolAddress(&pWd0, gWdep0);
    cudaGetSymbolAddress(&pR0, g_rowsum0); cudaGetSymbolAddress(&pR1, g_rowsum1);
    cudaGetSymbolAddress(&pSL, g_slog);    cudaGetSymbolAddress(&pDL, g_dlog);
    cudaGetSymbolAddress(&pRL, g_rlog);

    cudaFuncSetAttribute(tc_gemm1<1, false>,
                         cudaFuncAttributeMaxDynamicSharedMemorySize, SM1);
    cudaFuncSetAttribute(tc_gemm1<SUPC, true>,
                         cudaFuncAttributeMaxDynamicSharedMemorySize, SM1);
    cudaFuncSetAttribute(tc_gemm_dep_re,
                         cudaFuncAttributeMaxDynamicSharedMemorySize, SM_CMB);

    zero_scratch<<<512, 256>>>();
    split_x_mean<<<512, 256>>>(X);
    transpose_split_w<<<dim3(HH / 32, H / 32), 256>>>(tokW1, HH, 1,
        (__half*)pWt0, (__half*)pWt0);
    transpose_split_w<<<dim3(HH / 32, H / 32), 256>>>(effW1, HH, 1,
        (__half*)pWe0, (__half*)pWe0);
    transpose_split_w<<<dim3(H / 32, H / 32), 256>>>(supW1, H, 2,
        (__half*)pWs0, (__half*)pWs1);
    transpose_split_w<<<dim3(H / 32, H / 32), 256>>>(depW1, H, 1,
        (__half*)pWd0, (__half*)pWd0);

    ctx_task_kernel<<<dim3(BATCH, 2), 1024>>>(ctxW1, ctxb1, ctxW2, ctxb2,
                                              taskW1, taskb1, taskW2, taskb2, out);

    // tok / eff: single-pass fp16, 512-thread CTAs
    tc_gemm1<1, false><<<dim3(HH / 256, M_ROWS / 128), TG, SM1>>>(
        (const __half*)pX0, (const __half*)pWt0,
        tokb1, tokW2, nullptr, (float*)pR0, nullptr, nullptr, nullptr, HH);
    tc_gemm1<1, false><<<dim3(HH / 256, M_ROWS / 128), TG, SM1>>>(
        (const __half*)pX0, (const __half*)pWe0,
        effb1, effW2, nullptr, (float*)pR1, nullptr, nullptr, nullptr, HH);
    finalize_tokeff<<<M_ROWS / 256, 256>>>(out, tokb2, effb2);

    // sup: single-pass fp16 with extra features
    tc_gemm1<SUPC, true><<<dim3(H / 256, M_ROWS / 128), TG, SM1>>>(
        (const __half*)pX0, (const __half*)pWs0,
        supb1, supW2, supW1, (float*)pSL,
        out + OFF_TOK, out + OFF_CTX, out + OFF_TASK, H);

    softmax_sup_flag<<<M_ROWS / 256, 256>>>(out, supb2);

    // combined: recheck blocks (first wave) + dep GEMM blocks — overlapped
    tc_gemm_dep_re<<<RE_BLOCKS + 8 * (M_ROWS / 128), TG, SM_CMB>>>(
        (const __half*)pX0, (const __half*)pX1, (const __half*)pWd0,
        (const __half*)pWs0, (const __half*)pWs1,
        depb1, depW2, depW1, supb1, supW2, supW1,
        (float*)pDL, (float*)pRL,
        out + OFF_TOK, out + OFF_CTX, out + OFF_TASK);

    softmax_dep_refinal<<<M_ROWS / 256, 256>>>(out, depb2, supb2);

    (void)in_sizes; (void)n_in; (void)out_size;
}

// round 13
// speedup vs baseline: 1.0818x; 1.0818x over previous
#include <cuda_runtime.h>
#include <cuda_fp16.h>
#include <cstdint>
#include <math.h>

#define H      2048
#define HH     1024
#define BATCH  4
#define SEQ    4096
#define M_ROWS 16384
#define SUPC   4
#define HEADSC 8

// d_out float offsets (tuple order, flattened)
#define OFF_TOK  0
#define OFF_CTX  16384
#define OFF_TASK 16388
#define OFF_SUP  16392
#define OFF_DEP  81928
#define OFF_EFF  213000
#define OFF_MASK 229384

#define RECHECK_MARGIN 0.005f
#define RE_MAX_ROWS    4096
#define RE_BLOCKS      256       // 32 m-blocks x 8 n-blocks

// ================= scratch (no allocations allowed) =================
__device__ float g_ctxsum[BATCH * H];
__device__ float g_rowsum0[M_ROWS];
__device__ float g_rowsum1[M_ROWS];
__device__ float g_slog[M_ROWS * SUPC];
__device__ float g_dlog[M_ROWS * HEADSC];
__device__ int   g_count;
__device__ int   g_rowmap[M_ROWS];
__device__ float g_rlog[M_ROWS * SUPC];

__device__ __half gX0[M_ROWS * H];
__device__ __half gX1[M_ROWS * H];
__device__ __half gWtok0[HH * H];
__device__ __half gWeff0[HH * H];
__device__ __half gWsup0[H * H];
__device__ __half gWsup1[H * H];
__device__ __half gWdep0[H * H];

__device__ __forceinline__ float gelu_exact(float x) {
    return 0.5f * x * (1.0f + erff(x * 0.70710678118654752f));
}
__device__ __forceinline__ float sigmoidf_(float x) {
    return 1.0f / (1.0f + expf(-x));
}
__device__ __forceinline__ uint32_t smem_to_u32(const void* p) {
    uint32_t a;
    asm("{ .reg .u64 t; cvta.to.shared.u64 t, %1; cvt.u32.u64 %0, t; }" : "=r"(a) : "l"(p));
    return a;
}
#define SWZ(off) ((off) ^ (((off) >> 3) & 0x70))

#define LDSM4(r, addr) \
    asm volatile("ldmatrix.sync.aligned.m8n8.x4.shared.b16 {%0,%1,%2,%3}, [%4];" \
                 : "=r"((r)[0]), "=r"((r)[1]), "=r"((r)[2]), "=r"((r)[3]) : "r"(addr))

static constexpr int ASZ_C = 128 * 128;   // 16KB: A tile (128 rows x 64 fp16)
static constexpr int BSZ_C = 256 * 128;   // 32KB: B tile (256 rows x 64 fp16)
static constexpr int STG1  = ASZ_C + BSZ_C;   // 48KB stage
static constexpr int SM1   = 3 * STG1;        // 147456
static constexpr int STG3  = 2 * STG1;        // 96KB (recheck: 2 parts)
static constexpr int SM_CMB = 2 * STG3;       // 196608

// ---- round-9 winner config: 8 warps, warp grid 2(m) x 4(n), warp tile 64x64 ----
__device__ __forceinline__ void mmas(float (&acc)[4][8][4],
                                     uint32_t (&a)[4][4], uint32_t (&b)[4][4]) {
    #pragma unroll
    for (int ms = 0; ms < 4; ms++)
        #pragma unroll
        for (int ns = 0; ns < 8; ns++) {
            uint32_t b0 = b[ns >> 1][ns & 1];
            uint32_t b1 = b[ns >> 1][2 + (ns & 1)];
            asm volatile(
                "mma.sync.aligned.m16n8k16.row.col.f32.f16.f16.f32 "
                "{%0,%1,%2,%3}, {%4,%5,%6,%7}, {%8,%9}, {%0,%1,%2,%3};"
                : "+f"(acc[ms][ns][0]), "+f"(acc[ms][ns][1]),
                  "+f"(acc[ms][ns][2]), "+f"(acc[ms][ns][3])
                : "r"(a[ms][0]), "r"(a[ms][1]), "r"(a[ms][2]), "r"(a[ms][3]),
                  "r"(b0), "r"(b1));
        }
}

__device__ __forceinline__ void ldfrag(uint32_t Ab, uint32_t Bb, int wm, int wn,
                                       int r16, int kb,
                                       uint32_t (&a)[4][4], uint32_t (&b)[4][4]) {
    #pragma unroll
    for (int ms = 0; ms < 4; ms++)
        LDSM4(a[ms], Ab + SWZ((wm * 64 + ms * 16 + r16) * 128 + kb));
    #pragma unroll
    for (int nt = 0; nt < 4; nt++)
        LDSM4(b[nt], Bb + SWZ((wn * 64 + nt * 16 + r16) * 128 + kb));
}

__device__ __forceinline__ void compute_chunk1(uint32_t Ab, uint32_t Bb,
        float (&acc)[4][8][4], int wm, int wn, int lane) {
    const int r16 = lane & 15;
    const int kg  = (lane >> 4) * 16;
    #pragma unroll
    for (int ks = 0; ks < 4; ks++) {
        const int kb = ks * 32 + kg;
        uint32_t a[4][4], b[4][4];
        ldfrag(Ab, Bb, wm, wn, r16, kb, a, b);
        mmas(acc, a, b);
    }
}

// ---- loaders ----
__device__ __forceinline__ void load1(uint32_t dstbase, int kc, int m0, int n0,
                                      int tid, const __half* __restrict__ A0,
                                      const __half* __restrict__ B0) {
    for (int idx = tid; idx < 3072; idx += 256) {
        uint32_t dst;
        const __half* src;
        if (idx < 1024) {
            int r = idx >> 3, i = idx & 7;
            dst = dstbase + SWZ(r * 128 + i * 16);
            src = A0 + (size_t)(m0 + r) * H + kc * 64 + i * 8;
        } else {
            int j = idx - 1024;
            int r = j >> 3, i = j & 7;
            dst = dstbase + ASZ_C + SWZ(r * 128 + i * 16);
            src = B0 + (size_t)(n0 + r) * H + kc * 64 + i * 8;
        }
        asm volatile("cp.async.cg.shared.global [%0], [%1], 16;" :: "r"(dst), "l"(src) : "memory");
    }
    asm volatile("cp.async.commit_group;" ::: "memory");
}

__device__ __forceinline__ void load3(uint32_t dstbase, int kc, int tid,
                                      const int* rs, int n0,
                                      const __half* __restrict__ A0,
                                      const __half* __restrict__ A1,
                                      const __half* __restrict__ B0,
                                      const __half* __restrict__ B1) {
    for (int idx = tid; idx < 2048 + 4096; idx += 256) {
        uint32_t dst;
        const __half* src;
        if (idx < 2048) {
            int s = idx >> 10;
            int r = (idx & 1023) >> 3;
            int i = idx & 7;
            dst = dstbase + s * ASZ_C + SWZ(r * 128 + i * 16);
            src = (s ? A1 : A0) + (size_t)rs[r] * H + kc * 64 + i * 8;
        } else {
            int j = idx - 2048;
            int s = j >> 11;
            int r = (j & 2047) >> 3;
            int i = j & 7;
            dst = dstbase + 2 * ASZ_C + s * BSZ_C + SWZ(r * 128 + i * 16);
            src = (s ? B1 : B0) + (size_t)(n0 + r) * H + kc * 64 + i * 8;
        }
        asm volatile("cp.async.cg.shared.global [%0], [%1], 16;" :: "r"(dst), "l"(src) : "memory");
    }
    asm volatile("cp.async.commit_group;" ::: "memory");
}

// ---- single-pass GEMM body (compile-time C/EX), 256 threads ----
template <int C, bool EX>
__device__ __forceinline__ void gemm1_body(
    uint32_t base, int m0, int n0, int tid,
    const __half* __restrict__ A0, const __half* __restrict__ B0,
    const float* __restrict__ bias1, const float* __restrict__ W2,
    const float* __restrict__ W1o, float* __restrict__ accout,
    const float* __restrict__ tcv, const float* __restrict__ ccv,
    const float* __restrict__ tkv, int Ntot)
{
    constexpr int NC = H / 64;
    const int lane = tid & 31;
    const int wid  = tid >> 5;
    const int wm   = wid >> 2;
    const int wn   = wid & 3;

    float acc[4][8][4];
    #pragma unroll
    for (int a = 0; a < 4; a++)
        #pragma unroll
        for (int b = 0; b < 8; b++)
            #pragma unroll
            for (int c = 0; c < 4; c++) acc[a][b][c] = 0.f;

    load1(base + 0 * STG1, 0, m0, n0, tid, A0, B0);
    load1(base + 1 * STG1, 1, m0, n0, tid, A0, B0);

    for (int c = 0; c < NC; c++) {
        if (c + 2 < NC)
            load1(base + ((c + 2) % 3) * STG1, c + 2, m0, n0, tid, A0, B0);
        if (c + 2 < NC)      asm volatile("cp.async.wait_group %0;" :: "n"(2) : "memory");
        else if (c + 1 < NC) asm volatile("cp.async.wait_group %0;" :: "n"(1) : "memory");
        else                 asm volatile("cp.async.wait_group %0;" :: "n"(0) : "memory");
        __syncthreads();
        const uint32_t sb = base + (c % 3) * STG1;
        compute_chunk1(sb, sb + ASZ_C, acc, wm, wn, lane);
        __syncthreads();
    }

    float ccs = 0.f, tks = 0.f;
    if (EX) { ccs = ccv[m0 >> 12]; tks = tkv[m0 >> 12]; }

    #pragma unroll
    for (int ms = 0; ms < 4; ms++) {
        #pragma unroll
        for (int hh = 0; hh < 2; hh++) {
            const int r = m0 + wm * 64 + ms * 16 + (lane >> 2) + hh * 8;
            float tc = 0.f;
            if (EX) tc = tcv[r];
            float pc[C];
            #pragma unroll
            for (int ci = 0; ci < C; ci++) pc[ci] = 0.f;
            #pragma unroll
            for (int ns = 0; ns < 8; ns++) {
                #pragma unroll
                for (int e = 0; e < 2; e++) {
                    const int n = n0 + wn * 64 + ns * 8 + (lane & 3) * 2 + e;
                    float v = acc[ms][ns][hh * 2 + e] + bias1[n];
                    if (EX) {
                        v += tc  * W1o[(size_t)2048 * Ntot + n]
                           + ccs * W1o[(size_t)2049 * Ntot + n]
                           + tks * W1o[(size_t)2050 * Ntot + n];
                    }
                    float h = gelu_exact(v);
                    #pragma unroll
                    for (int ci = 0; ci < C; ci++)
                        pc[ci] = fmaf(h, W2[(size_t)n * C + ci], pc[ci]);
                }
            }
            #pragma unroll
            for (int ci = 0; ci < C; ci++) {
                pc[ci] += __shfl_xor_sync(0xffffffffu, pc[ci], 1);
                pc[ci] += __shfl_xor_sync(0xffffffffu, pc[ci], 2);
            }
            if ((lane & 3) == 0) {
                #pragma unroll
                for (int ci = 0; ci < C; ci++)
                    atomicAdd(&accout[(size_t)r * C + ci], pc[ci]);
            }
        }
    }
}

// ---- fused tok+eff GEMM: bid-dispatch, same compile-time body ----
// grid.x: 0-3 tok n-blocks, 4-7 eff n-blocks
__global__ void __launch_bounds__(256, 1)
tc_gemm_tokeff(const __half* __restrict__ X0,
               const __half* __restrict__ Wt0, const __half* __restrict__ We0,
               const float* __restrict__ tokb1, const float* __restrict__ tokW2,
               const float* __restrict__ effb1, const float* __restrict__ effW2,
               float* __restrict__ r0, float* __restrict__ r1)
{
    extern __shared__ char smem[];
    const int seg = blockIdx.x >> 2;
    const int n0  = (blockIdx.x & 3) * 256;
    gemm1_body<1, false>(smem_to_u32(smem), blockIdx.y * 128, n0, threadIdx.x,
                         X0, seg ? We0 : Wt0,
                         seg ? effb1 : tokb1, seg ? effW2 : tokW2,
                         nullptr, seg ? r1 : r0, nullptr, nullptr, nullptr, HH);
}

// ---- sup GEMM ----
template <int C, bool EX>
__global__ void __launch_bounds__(256, 1)
tc_gemm1(const __half* __restrict__ A0, const __half* __restrict__ B0,
         const float* __restrict__ bias1, const float* __restrict__ W2,
         const float* __restrict__ W1o, float* __restrict__ accout,
         const float* __restrict__ tcv, const float* __restrict__ ccv,
         const float* __restrict__ tkv, int Ntot)
{
    extern __shared__ char smem[];
    gemm1_body<C, EX>(smem_to_u32(smem), blockIdx.y * 128, blockIdx.x * 256,
                      threadIdx.x, A0, B0, bias1, W2, W1o, accout, tcv, ccv, tkv, Ntot);
}

// ---- gathered 3-term recheck body ----
__device__ __forceinline__ void recheck_body(
    uint32_t base, int m0, int n0, int tid, int* rowsm,
    const __half* __restrict__ A0, const __half* __restrict__ A1,
    const __half* __restrict__ B0, const __half* __restrict__ B1,
    const float* __restrict__ bias1, const float* __restrict__ W2,
    const float* __restrict__ W1o, float* __restrict__ accout,
    const float* __restrict__ tcv, const float* __restrict__ ccv,
    const float* __restrict__ tkv)
{
    constexpr int NC = H / 64;
    const int lane = tid & 31;
    const int wid  = tid >> 5;
    const int wm   = wid >> 2;
    const int wn   = wid & 3;

    for (int i = tid; i < 128; i += 256) rowsm[i] = g_rowmap[m0 + i];
    __syncthreads();

    float acc[4][8][4];
    #pragma unroll
    for (int a = 0; a < 4; a++)
        #pragma unroll
        for (int b = 0; b < 8; b++)
            #pragma unroll
            for (int c = 0; c < 4; c++) acc[a][b][c] = 0.f;

    load3(base, 0, tid, rowsm, n0, A0, A1, B0, B1);

    for (int c = 0; c < NC; c++) {
        if (c + 1 < NC)
            load3(base + ((c + 1) & 1) * STG3, c + 1, tid, rowsm, n0, A0, A1, B0, B1);
        if (c + 1 < NC) asm volatile("cp.async.wait_group %0;" :: "n"(1) : "memory");
        else            asm volatile("cp.async.wait_group %0;" :: "n"(0) : "memory");
        __syncthreads();
        const uint32_t sb = base + (c & 1) * STG3;
        const uint32_t Ab = sb, Bb = sb + 2 * ASZ_C;
        {
            const int r16 = lane & 15;
            const int kg  = (lane >> 4) * 16;
            #pragma unroll
            for (int ks = 0; ks < 4; ks++) {
                const int kb = ks * 32 + kg;
                uint32_t af0[4][4], bf0[4][4];
                #pragma unroll
                for (int ms = 0; ms < 4; ms++)
                    LDSM4(af0[ms], Ab + SWZ((wm * 64 + ms * 16 + r16) * 128 + kb));
                #pragma unroll
                for (int nt = 0; nt < 4; nt++)
                    LDSM4(bf0[nt], Bb + SWZ((wn * 64 + nt * 16 + r16) * 128 + kb));
                mmas(acc, af0, bf0);
                uint32_t af1[4][4];
                #pragma unroll
                for (int ms = 0; ms < 4; ms++)
                    LDSM4(af1[ms], Ab + ASZ_C + SWZ((wm * 64 + ms * 16 + r16) * 128 + kb));
                mmas(acc, af1, bf0);
                uint32_t bf1[4][4];
                #pragma unroll
                for (int nt = 0; nt < 4; nt++)
                    LDSM4(bf1[nt], Bb + BSZ_C + SWZ((wn * 64 + nt * 16 + r16) * 128 + kb));
                mmas(acc, af0, bf1);
            }
        }
        __syncthreads();
    }

    #pragma unroll
    for (int ms = 0; ms < 4; ms++) {
        #pragma unroll
        for (int hh = 0; hh < 2; hh++) {
            const int slot = m0 + wm * 64 + ms * 16 + (lane >> 2) + hh * 8;
            const int rg   = rowsm[slot - m0];
            float tc = tcv[rg], ccs = ccv[rg >> 12], tks = tkv[rg >> 12];
            float pc[SUPC];
            #pragma unroll
            for (int ci = 0; ci < SUPC; ci++) pc[ci] = 0.f;
            #pragma unroll
            for (int ns = 0; ns < 8; ns++) {
                #pragma unroll
                for (int e = 0; e < 2; e++) {
                    const int n = n0 + wn * 64 + ns * 8 + (lane & 3) * 2 + e;
                    float v = acc[ms][ns][hh * 2 + e] + bias1[n];
                    v += tc  * W1o[(size_t)2048 * H + n]
                       + ccs * W1o[(size_t)2049 * H + n]
                       + tks * W1o[(size_t)2050 * H + n];
                    float h = gelu_exact(v);
                    #pragma unroll
                    for (int ci = 0; ci < SUPC; ci++)
                        pc[ci] = fmaf(h, W2[(size_t)n * SUPC + ci], pc[ci]);
                }
            }
            #pragma unroll
            for (int ci = 0; ci < SUPC; ci++) {
                pc[ci] += __shfl_xor_sync(0xffffffffu, pc[ci], 1);
                pc[ci] += __shfl_xor_sync(0xffffffffu, pc[ci], 2);
            }
            if ((lane & 3) == 0) {
                #pragma unroll
                for (int ci = 0; ci < SUPC; ci++)
                    atomicAdd(&accout[(size_t)slot * SUPC + ci], pc[ci]);
            }
        }
    }
}

// ---- combined dep GEMM + recheck (single launch -> overlap) ----
__global__ void __launch_bounds__(256, 1)
tc_gemm_dep_re(const __half* __restrict__ X0, const __half* __restrict__ X1,
               const __half* __restrict__ Wd0,
               const __half* __restrict__ Ws0, const __half* __restrict__ Ws1,
               const float* __restrict__ depb1, const float* __restrict__ depW2,
               const float* __restrict__ depW1,
               const float* __restrict__ supb1, const float* __restrict__ supW2,
               const float* __restrict__ supW1,
               float* __restrict__ dlog, float* __restrict__ rlog,
               const float* __restrict__ tcv, const float* __restrict__ ccv,
               const float* __restrict__ tkv)
{
    extern __shared__ char smem[];
    __shared__ int rowsm[128];
    const uint32_t base = smem_to_u32(smem);
    const int bid = blockIdx.x;
    const int tid = threadIdx.x;

    if (bid < RE_BLOCKS) {
        const int m0 = (bid >> 3) * 128;
        const int n0 = (bid & 7) * 256;
        if (m0 >= g_count) return;
        recheck_body(base, m0, n0, tid, rowsm, X0, X1, Ws0, Ws1,
                     supb1, supW2, supW1, rlog, tcv, ccv, tkv);
    } else {
        const int b2 = bid - RE_BLOCKS;
        const int m0 = (b2 >> 3) * 128;
        const int n0 = (b2 & 7) * 256;
        gemm1_body<HEADSC, true>(base, m0, n0, tid, X0, Wd0,
                                 depb1, depW2, depW1, dlog, tcv, ccv, tkv, H);
    }
}

// ================= precompute kernels =================
__global__ void split_x_mean(const float* __restrict__ X) {
    int idx = blockIdx.x * blockDim.x + threadIdx.x;
    int d     = idx & (H - 1);
    int chunk = (idx >> 11) & 15;
    int b     = idx >> 15;
    size_t p = ((size_t)(b * SEQ + chunk * 256)) * H + d;
    float s = 0.f;
    #pragma unroll 4
    for (int t = 0; t < 256; t++) {
        float x = X[p];
        s += x;
        __half h = __float2half_rn(x);
        gX0[p] = h;
        gX1[p] = __float2half_rn(x - __half2float(h));
        p += H;
    }
    atomicAdd(&g_ctxsum[b * H + d], s);
}

// fused transpose of all 4 W1 matrices (blockIdx.z = job)
__global__ void transpose_all(const float* __restrict__ tokW1,
                              const float* __restrict__ effW1,
                              const float* __restrict__ supW1,
                              const float* __restrict__ depW1,
                              __half* __restrict__ o_tok, __half* __restrict__ o_eff,
                              __half* __restrict__ o_sup0, __half* __restrict__ o_sup1,
                              __half* __restrict__ o_dep)
{
    __shared__ float t[32][33];
    const int job = blockIdx.z;
    const float* W; int N; int nsplit; __half *o0, *o1;
    if      (job == 0) { W = tokW1; N = HH; nsplit = 1; o0 = o_tok;  o1 = o_tok;  }
    else if (job == 1) { W = effW1; N = HH; nsplit = 1; o0 = o_eff;  o1 = o_eff;  }
    else if (job == 2) { W = supW1; N = H;  nsplit = 2; o0 = o_sup0; o1 = o_sup1; }
    else               { W = depW1; N = H;  nsplit = 1; o0 = o_dep;  o1 = o_dep;  }

    int n0 = blockIdx.x * 32, k0 = blockIdx.y * 32;
    if (n0 >= N) return;
    int tx = threadIdx.x & 31, ty = threadIdx.x >> 5;
    #pragma unroll
    for (int s = 0; s < 32; s += 8)
        t[ty + s][tx] = W[(size_t)(k0 + ty + s) * N + n0 + tx];
    __syncthreads();
    #pragma unroll
    for (int s = 0; s < 32; s += 8) {
        int n = n0 + ty + s, k = k0 + tx;
        float x = t[tx][ty + s];
        __half hh = __float2half_rn(x);
        o0[(size_t)n * H + k] = hh;
        if (nsplit == 2) {
            float r = x - __half2float(hh);
            o1[(size_t)n * H + k] = __float2half_rn(r);
        }
    }
}

__global__ void zero_scratch() {
    int i = blockIdx.x * blockDim.x + threadIdx.x;
    if (i == 0)               g_count = 0;
    if (i < BATCH * H)        g_ctxsum[i] = 0.f;
    if (i < M_ROWS)         { g_rowsum0[i] = 0.f; g_rowsum1[i] = 0.f; g_rowmap[i] = 0; }
    if (i < M_ROWS * SUPC)  { g_slog[i] = 0.f; g_rlog[i] = 0.f; }
    if (i < M_ROWS * HEADSC)  g_dlog[i] = 0.f;
}

__global__ void ctx_task_kernel(
    const float* __restrict__ cW1, const float* __restrict__ cb1,
    const float* __restrict__ cW2, const float* __restrict__ cb2,
    const float* __restrict__ tW1, const float* __restrict__ tb1,
    const float* __restrict__ tW2, const float* __restrict__ tb2,
    float* __restrict__ out)
{
    __shared__ float emb[H];
    __shared__ float red[1024];
    int b = blockIdx.x, which = blockIdx.y;
    const float* W1 = which ? tW1 : cW1;
    const float* b1 = which ? tb1 : cb1;
    const float* W2 = which ? tW2 : cW2;
    const float* b2 = which ? tb2 : cb2;
    int tid = threadIdx.x;
    for (int i = tid; i < H; i += 1024)
        emb[i] = g_ctxsum[b * H + i] * (1.0f / SEQ);
    __syncthreads();

    float a = b1[tid];
    #pragma unroll 4
    for (int k = 0; k < H; k++)
        a = fmaf(emb[k], W1[(size_t)k * HH + tid], a);
    red[tid] = gelu_exact(a) * W2[tid];
    __syncthreads();
    for (int off = 512; off > 0; off >>= 1) {
        if (tid < off) red[tid] += red[tid + off];
        __syncthreads();
    }
    if (tid == 0)
        out[(which ? OFF_TASK : OFF_CTX) + b] = sigmoidf_(red[0] + b2[0]);
}

// ================= small finalize kernels =================
__global__ void finalize_tokeff(float* __restrict__ out,
                                const float* __restrict__ tokb2,
                                const float* __restrict__ effb2)
{
    int r = blockIdx.x * blockDim.x + threadIdx.x;
    if (r < M_ROWS) {
        out[OFF_TOK + r] = sigmoidf_(g_rowsum0[r] + tokb2[0]);
        out[OFF_EFF + r] = sigmoidf_(g_rowsum1[r] + effb2[0]);
    }
}

__global__ void softmax_sup_flag(float* __restrict__ out,
                                 const float* __restrict__ supb2)
{
    int r = blockIdx.x * blockDim.x + threadIdx.x;
    if (r >= M_ROWS) return;
    float l[SUPC];
    float m = -1e30f;
    #pragma unroll
    for (int c = 0; c < SUPC; c++) {
        l[c] = g_slog[(size_t)r * SUPC + c] + supb2[c];
        m = fmaxf(m, l[c]);
    }
    float s = 0.f;
    #pragma unroll
    for (int c = 0; c < SUPC; c++) { l[c] = expf(l[c] - m); s += l[c]; }
    float inv = 1.f / s;
    float eff = out[OFF_EFF + r];
    bool flag = false;
    #pragma unroll
    for (int c = 0; c < SUPC; c++) {
        float w = l[c] * inv;
        if (fabsf(w - 0.2f) < RECHECK_MARGIN) flag = true;
        out[OFF_SUP  + (size_t)r * SUPC + c] = w;
        out[OFF_MASK + (size_t)r * SUPC + c] = (w > 0.2f) ? eff : 0.f;
    }
    if (flag) {
        int slot = atomicAdd(&g_count, 1);
        if (slot < M_ROWS) g_rowmap[slot] = r;
    }
}

__global__ void softmax_dep_refinal(float* __restrict__ out,
                                    const float* __restrict__ depb2,
                                    const float* __restrict__ supb2)
{
    int r = blockIdx.x * blockDim.x + threadIdx.x;
    if (r >= M_ROWS) return;
    {
        float l[HEADSC];
        float m = -1e30f;
        #pragma unroll
        for (int c = 0; c < HEADSC; c++) {
            l[c] = g_dlog[(size_t)r * HEADSC + c] + depb2[c];
            m = fmaxf(m, l[c]);
        }
        float s = 0.f;
        #pragma unroll
        for (int c = 0; c < HEADSC; c++) { l[c] = expf(l[c] - m); s += l[c]; }
        float inv = 1.f / s;
        #pragma unroll
        for (int c = 0; c < HEADSC; c++)
            out[OFF_DEP + (size_t)r * HEADSC + c] = l[c] * inv;
    }
    int t = r;
    if (t < g_count && t < RE_MAX_ROWS) {
        int rr = g_rowmap[t];
        float l[SUPC];
        float m = -1e30f;
        #pragma unroll
        for (int c = 0; c < SUPC; c++) {
            l[c] = g_rlog[(size_t)t * SUPC + c] + supb2[c];
            m = fmaxf(m, l[c]);
        }
        float s = 0.f;
        #pragma unroll
        for (int c = 0; c < SUPC; c++) { l[c] = expf(l[c] - m); s += l[c]; }
        float inv = 1.f / s;
        float eff = out[OFF_EFF + rr];
        #pragma unroll
        for (int c = 0; c < SUPC; c++) {
            float w = l[c] * inv;
            out[OFF_SUP  + (size_t)rr * SUPC + c] = w;
            out[OFF_MASK + (size_t)rr * SUPC + c] = (w > 0.2f) ? eff : 0.f;
        }
    }
}

// ================= launch =================
extern "C" void kernel_launch(void* const* d_in, const int* in_sizes, int n_in,
                              void* d_out, int out_size)
{
    const float* X      = (const float*)d_in[0];
    const float* tokW1  = (const float*)d_in[1];
    const float* tokb1  = (const float*)d_in[2];
    const float* tokW2  = (const float*)d_in[3];
    const float* tokb2  = (const float*)d_in[4];
    const float* ctxW1  = (const float*)d_in[5];
    const float* ctxb1  = (const float*)d_in[6];
    const float* ctxW2  = (const float*)d_in[7];
    const float* ctxb2  = (const float*)d_in[8];
    const float* taskW1 = (const float*)d_in[9];
    const float* taskb1 = (const float*)d_in[10];
    const float* taskW2 = (const float*)d_in[11];
    const float* taskb2 = (const float*)d_in[12];
    const float* effW1  = (const float*)d_in[13];
    const float* effb1  = (const float*)d_in[14];
    const float* effW2  = (const float*)d_in[15];
    const float* effb2  = (const float*)d_in[16];
    const float* supW1  = (const float*)d_in[17];
    const float* supb1  = (const float*)d_in[18];
    const float* supW2  = (const float*)d_in[19];
    const float* supb2  = (const float*)d_in[20];
    const float* depW1  = (const float*)d_in[21];
    const float* depb1  = (const float*)d_in[22];
    const float* depW2  = (const float*)d_in[23];
    const float* depb2  = (const float*)d_in[24];
    float* out = (float*)d_out;

    void *pX0, *pX1, *pWt0, *pWe0, *pWs0, *pWs1, *pWd0;
    void *pR0, *pR1, *pSL, *pDL, *pRL;
    cudaGetSymbolAddress(&pX0, gX0);   cudaGetSymbolAddress(&pX1, gX1);
    cudaGetSymbolAddress(&pWt0, gWtok0);
    cudaGetSymbolAddress(&pWe0, gWeff0);
    cudaGetSymbolAddress(&pWs0, gWsup0); cudaGetSymbolAddress(&pWs1, gWsup1);
    cudaGetSymbolAddress(&pWd0, gWdep0);
    cudaGetSymbolAddress(&pR0, g_rowsum0); cudaGetSymbolAddress(&pR1, g_rowsum1);
    cudaGetSymbolAddress(&pSL, g_slog);    cudaGetSymbolAddress(&pDL, g_dlog);
    cudaGetSymbolAddress(&pRL, g_rlog);

    cudaFuncSetAttribute(tc_gemm_tokeff,
                         cudaFuncAttributeMaxDynamicSharedMemorySize, SM1);
    cudaFuncSetAttribute(tc_gemm1<SUPC, true>,
                         cudaFuncAttributeMaxDynamicSharedMemorySize, SM1);
    cudaFuncSetAttribute(tc_gemm_dep_re,
                         cudaFuncAttributeMaxDynamicSharedMemorySize, SM_CMB);

    zero_scratch<<<512, 256>>>();
    split_x_mean<<<512, 256>>>(X);
    transpose_all<<<dim3(H / 32, H / 32, 4), 256>>>(
        tokW1, effW1, supW1, depW1,
        (__half*)pWt0, (__half*)pWe0, (__half*)pWs0, (__half*)pWs1, (__half*)pWd0);

    ctx_task_kernel<<<dim3(BATCH, 2), 1024>>>(ctxW1, ctxb1, ctxW2, ctxb2,
                                              taskW1, taskb1, taskW2, taskb2, out);

    // fused tok + eff GEMM (one launch, compile-time body, pointer dispatch)
    tc_gemm_tokeff<<<dim3(8, M_ROWS / 128), 256, SM1>>>(
        (const __half*)pX0, (const __half*)pWt0, (const __half*)pWe0,
        tokb1, tokW2, effb1, effW2, (float*)pR0, (float*)pR1);
    finalize_tokeff<<<M_ROWS / 256, 256>>>(out, tokb2, effb2);

    // sup: single-pass fp16 with extra features
    tc_gemm1<SUPC, true><<<dim3(H / 256, M_ROWS / 128), 256, SM1>>>(
        (const __half*)pX0, (const __half*)pWs0,
        supb1, supW2, supW1, (float*)pSL,
        out + OFF_TOK, out + OFF_CTX, out + OFF_TASK, H);

    softmax_sup_flag<<<M_ROWS / 256, 256>>>(out, supb2);

    // combined: recheck blocks (first wave) + dep GEMM blocks — overlapped
    tc_gemm_dep_re<<<RE_BLOCKS + 8 * (M_ROWS / 128), 256, SM_CMB>>>(
        (const __half*)pX0, (const __half*)pX1, (const __half*)pWd0,
        (const __half*)pWs0, (const __half*)pWs1,
        depb1, depW2, depW1, supb1, supW2, supW1,
        (float*)pDL, (float*)pRL,
        out + OFF_TOK, out + OFF_CTX, out + OFF_TASK);

    softmax_dep_refinal<<<M_ROWS / 256, 256>>>(out, depb2, supb2);

    (void)in_sizes; (void)n_in; (void)out_size;
}

// round 14
// speedup vs baseline: 1.2547x; 1.1598x over previous
#include <cuda_runtime.h>
#include <cuda_fp16.h>
#include <cstdint>
#include <math.h>

#define H      2048
#define HH     1024
#define BATCH  4
#define SEQ    4096
#define M_ROWS 16384
#define SUPC   4
#define HEADSC 8

// d_out float offsets (tuple order, flattened)
#define OFF_TOK  0
#define OFF_CTX  16384
#define OFF_TASK 16388
#define OFF_SUP  16392
#define OFF_DEP  81928
#define OFF_EFF  213000
#define OFF_MASK 229384

#define RECHECK_MARGIN 0.005f
#define RE_MAX_ROWS    4096
#define RE_BLOCKS      256       // 32 m-blocks x 8 n-blocks

// ================= scratch (no allocations allowed) =================
__device__ float g_ctxsum[BATCH * H];
__device__ float g_hid[8][HH];           // ctx/task hidden partials
__device__ float g_rowsum0[M_ROWS];
__device__ float g_rowsum1[M_ROWS];
__device__ float g_slog[M_ROWS * SUPC];
__device__ float g_dlog[M_ROWS * HEADSC];
__device__ int   g_count;
__device__ int   g_rowmap[M_ROWS];
__device__ float g_rlog[M_ROWS * SUPC];

__device__ __half gX0[M_ROWS * H];
__device__ __half gX1[M_ROWS * H];
__device__ __half gWtok0[HH * H];
__device__ __half gWeff0[HH * H];
__device__ __half gWsup0[H * H];
__device__ __half gWsup1[H * H];
__device__ __half gWdep0[H * H];

__device__ __forceinline__ float gelu_exact(float x) {
    return 0.5f * x * (1.0f + erff(x * 0.70710678118654752f));
}
__device__ __forceinline__ float sigmoidf_(float x) {
    return 1.0f / (1.0f + expf(-x));
}
__device__ __forceinline__ uint32_t smem_to_u32(const void* p) {
    uint32_t a;
    asm("{ .reg .u64 t; cvta.to.shared.u64 t, %1; cvt.u32.u64 %0, t; }" : "=r"(a) : "l"(p));
    return a;
}
#define SWZ(off) ((off) ^ (((off) >> 3) & 0x70))

#define LDSM4(r, addr) \
    asm volatile("ldmatrix.sync.aligned.m8n8.x4.shared.b16 {%0,%1,%2,%3}, [%4];" \
                 : "=r"((r)[0]), "=r"((r)[1]), "=r"((r)[2]), "=r"((r)[3]) : "r"(addr))

static constexpr int ASZ_C = 128 * 128;   // 16KB: A tile (128 rows x 64 fp16)
static constexpr int BSZ_C = 256 * 128;   // 32KB: B tile (256 rows x 64 fp16)
static constexpr int STG1  = ASZ_C + BSZ_C;   // 48KB stage
static constexpr int SM1   = 3 * STG1;        // 147456
static constexpr int STG3  = 2 * STG1;        // 96KB (recheck: 2 parts)
static constexpr int SM_CMB = 2 * STG3;       // 196608

// ---- 8 warps, warp grid 2(m) x 4(n), warp tile 64x64 ----
__device__ __forceinline__ void mmas(float (&acc)[4][8][4],
                                     uint32_t (&a)[4][4], uint32_t (&b)[4][4]) {
    #pragma unroll
    for (int ms = 0; ms < 4; ms++)
        #pragma unroll
        for (int ns = 0; ns < 8; ns++) {
            uint32_t b0 = b[ns >> 1][ns & 1];
            uint32_t b1 = b[ns >> 1][2 + (ns & 1)];
            asm volatile(
                "mma.sync.aligned.m16n8k16.row.col.f32.f16.f16.f32 "
                "{%0,%1,%2,%3}, {%4,%5,%6,%7}, {%8,%9}, {%0,%1,%2,%3};"
                : "+f"(acc[ms][ns][0]), "+f"(acc[ms][ns][1]),
                  "+f"(acc[ms][ns][2]), "+f"(acc[ms][ns][3])
                : "r"(a[ms][0]), "r"(a[ms][1]), "r"(a[ms][2]), "r"(a[ms][3]),
                  "r"(b0), "r"(b1));
        }
}

__device__ __forceinline__ void ldfrag(uint32_t Ab, uint32_t Bb, int wm, int wn,
                                       int r16, int kb,
                                       uint32_t (&a)[4][4], uint32_t (&b)[4][4]) {
    #pragma unroll
    for (int ms = 0; ms < 4; ms++)
        LDSM4(a[ms], Ab + SWZ((wm * 64 + ms * 16 + r16) * 128 + kb));
    #pragma unroll
    for (int nt = 0; nt < 4; nt++)
        LDSM4(b[nt], Bb + SWZ((wn * 64 + nt * 16 + r16) * 128 + kb));
}

__device__ __forceinline__ void compute_chunk1(uint32_t Ab, uint32_t Bb,
        float (&acc)[4][8][4], int wm, int wn, int lane) {
    const int r16 = lane & 15;
    const int kg  = (lane >> 4) * 16;
    #pragma unroll
    for (int ks = 0; ks < 4; ks++) {
        const int kb = ks * 32 + kg;
        uint32_t a[4][4], b[4][4];
        ldfrag(Ab, Bb, wm, wn, r16, kb, a, b);
        mmas(acc, a, b);
    }
}

// ---- loaders ----
__device__ __forceinline__ void load1(uint32_t dstbase, int kc, int m0, int n0,
                                      int tid, const __half* __restrict__ A0,
                                      const __half* __restrict__ B0) {
    for (int idx = tid; idx < 3072; idx += 256) {
        uint32_t dst;
        const __half* src;
        if (idx < 1024) {
            int r = idx >> 3, i = idx & 7;
            dst = dstbase + SWZ(r * 128 + i * 16);
            src = A0 + (size_t)(m0 + r) * H + kc * 64 + i * 8;
        } else {
            int j = idx - 1024;
            int r = j >> 3, i = j & 7;
            dst = dstbase + ASZ_C + SWZ(r * 128 + i * 16);
            src = B0 + (size_t)(n0 + r) * H + kc * 64 + i * 8;
        }
        asm volatile("cp.async.cg.shared.global [%0], [%1], 16;" :: "r"(dst), "l"(src) : "memory");
    }
    asm volatile("cp.async.commit_group;" ::: "memory");
}

__device__ __forceinline__ void load3(uint32_t dstbase, int kc, int tid,
                                      const int* rs, int n0,
                                      const __half* __restrict__ A0,
                                      const __half* __restrict__ A1,
                                      const __half* __restrict__ B0,
                                      const __half* __restrict__ B1) {
    for (int idx = tid; idx < 2048 + 4096; idx += 256) {
        uint32_t dst;
        const __half* src;
        if (idx < 2048) {
            int s = idx >> 10;
            int r = (idx & 1023) >> 3;
            int i = idx & 7;
            dst = dstbase + s * ASZ_C + SWZ(r * 128 + i * 16);
            src = (s ? A1 : A0) + (size_t)rs[r] * H + kc * 64 + i * 8;
        } else {
            int j = idx - 2048;
            int s = j >> 11;
            int r = (j & 2047) >> 3;
            int i = j & 7;
            dst = dstbase + 2 * ASZ_C + s * BSZ_C + SWZ(r * 128 + i * 16);
            src = (s ? B1 : B0) + (size_t)(n0 + r) * H + kc * 64 + i * 8;
        }
        asm volatile("cp.async.cg.shared.global [%0], [%1], 16;" :: "r"(dst), "l"(src) : "memory");
    }
    asm volatile("cp.async.commit_group;" ::: "memory");
}

// ---- single-pass GEMM body (compile-time C/EX), 256 threads ----
template <int C, bool EX>
__device__ __forceinline__ void gemm1_body(
    uint32_t base, int m0, int n0, int tid,
    const __half* __restrict__ A0, const __half* __restrict__ B0,
    const float* __restrict__ bias1, const float* __restrict__ W2,
    const float* __restrict__ W1o, float* __restrict__ accout,
    const float* __restrict__ tcv, const float* __restrict__ ccv,
    const float* __restrict__ tkv, int Ntot)
{
    constexpr int NC = H / 64;
    const int lane = tid & 31;
    const int wid  = tid >> 5;
    const int wm   = wid >> 2;
    const int wn   = wid & 3;

    float acc[4][8][4];
    #pragma unroll
    for (int a = 0; a < 4; a++)
        #pragma unroll
        for (int b = 0; b < 8; b++)
            #pragma unroll
            for (int c = 0; c < 4; c++) acc[a][b][c] = 0.f;

    load1(base + 0 * STG1, 0, m0, n0, tid, A0, B0);
    load1(base + 1 * STG1, 1, m0, n0, tid, A0, B0);

    for (int c = 0; c < NC; c++) {
        if (c + 2 < NC)
            load1(base + ((c + 2) % 3) * STG1, c + 2, m0, n0, tid, A0, B0);
        if (c + 2 < NC)      asm volatile("cp.async.wait_group %0;" :: "n"(2) : "memory");
        else if (c + 1 < NC) asm volatile("cp.async.wait_group %0;" :: "n"(1) : "memory");
        else                 asm volatile("cp.async.wait_group %0;" :: "n"(0) : "memory");
        __syncthreads();
        const uint32_t sb = base + (c % 3) * STG1;
        compute_chunk1(sb, sb + ASZ_C, acc, wm, wn, lane);
        __syncthreads();
    }

    float ccs = 0.f, tks = 0.f;
    if (EX) { ccs = ccv[m0 >> 12]; tks = tkv[m0 >> 12]; }

    #pragma unroll
    for (int ms = 0; ms < 4; ms++) {
        #pragma unroll
        for (int hh = 0; hh < 2; hh++) {
            const int r = m0 + wm * 64 + ms * 16 + (lane >> 2) + hh * 8;
            float tc = 0.f;
            if (EX) tc = tcv[r];
            float pc[C];
            #pragma unroll
            for (int ci = 0; ci < C; ci++) pc[ci] = 0.f;
            #pragma unroll
            for (int ns = 0; ns < 8; ns++) {
                #pragma unroll
                for (int e = 0; e < 2; e++) {
                    const int n = n0 + wn * 64 + ns * 8 + (lane & 3) * 2 + e;
                    float v = acc[ms][ns][hh * 2 + e] + bias1[n];
                    if (EX) {
                        v += tc  * W1o[(size_t)2048 * Ntot + n]
                           + ccs * W1o[(size_t)2049 * Ntot + n]
                           + tks * W1o[(size_t)2050 * Ntot + n];
                    }
                    float h = gelu_exact(v);
                    #pragma unroll
                    for (int ci = 0; ci < C; ci++)
                        pc[ci] = fmaf(h, W2[(size_t)n * C + ci], pc[ci]);
                }
            }
            #pragma unroll
            for (int ci = 0; ci < C; ci++) {
                pc[ci] += __shfl_xor_sync(0xffffffffu, pc[ci], 1);
                pc[ci] += __shfl_xor_sync(0xffffffffu, pc[ci], 2);
            }
            if ((lane & 3) == 0) {
                #pragma unroll
                for (int ci = 0; ci < C; ci++)
                    atomicAdd(&accout[(size_t)r * C + ci], pc[ci]);
            }
        }
    }
}

// ---- fused tok+eff GEMM: bid-dispatch, same compile-time body ----
__global__ void __launch_bounds__(256, 1)
tc_gemm_tokeff(const __half* __restrict__ X0,
               const __half* __restrict__ Wt0, const __half* __restrict__ We0,
               const float* __restrict__ tokb1, const float* __restrict__ tokW2,
               const float* __restrict__ effb1, const float* __restrict__ effW2,
               float* __restrict__ r0, float* __restrict__ r1)
{
    extern __shared__ char smem[];
    const int seg = blockIdx.x >> 2;
    const int n0  = (blockIdx.x & 3) * 256;
    gemm1_body<1, false>(smem_to_u32(smem), blockIdx.y * 128, n0, threadIdx.x,
                         X0, seg ? We0 : Wt0,
                         seg ? effb1 : tokb1, seg ? effW2 : tokW2,
                         nullptr, seg ? r1 : r0, nullptr, nullptr, nullptr, HH);
}

// ---- sup GEMM ----
template <int C, bool EX>
__global__ void __launch_bounds__(256, 1)
tc_gemm1(const __half* __restrict__ A0, const __half* __restrict__ B0,
         const float* __restrict__ bias1, const float* __restrict__ W2,
         const float* __restrict__ W1o, float* __restrict__ accout,
         const float* __restrict__ tcv, const float* __restrict__ ccv,
         const float* __restrict__ tkv, int Ntot)
{
    extern __shared__ char smem[];
    gemm1_body<C, EX>(smem_to_u32(smem), blockIdx.y * 128, blockIdx.x * 256,
                      threadIdx.x, A0, B0, bias1, W2, W1o, accout, tcv, ccv, tkv, Ntot);
}

// ---- gathered 3-term recheck body ----
__device__ __forceinline__ void recheck_body(
    uint32_t base, int m0, int n0, int tid, int* rowsm,
    const __half* __restrict__ A0, const __half* __restrict__ A1,
    const __half* __restrict__ B0, const __half* __restrict__ B1,
    const float* __restrict__ bias1, const float* __restrict__ W2,
    const float* __restrict__ W1o, float* __restrict__ accout,
    const float* __restrict__ tcv, const float* __restrict__ ccv,
    const float* __restrict__ tkv)
{
    constexpr int NC = H / 64;
    const int lane = tid & 31;
    const int wid  = tid >> 5;
    const int wm   = wid >> 2;
    const int wn   = wid & 3;

    for (int i = tid; i < 128; i += 256) rowsm[i] = g_rowmap[m0 + i];
    __syncthreads();

    float acc[4][8][4];
    #pragma unroll
    for (int a = 0; a < 4; a++)
        #pragma unroll
        for (int b = 0; b < 8; b++)
            #pragma unroll
            for (int c = 0; c < 4; c++) acc[a][b][c] = 0.f;

    load3(base, 0, tid, rowsm, n0, A0, A1, B0, B1);

    for (int c = 0; c < NC; c++) {
        if (c + 1 < NC)
            load3(base + ((c + 1) & 1) * STG3, c + 1, tid, rowsm, n0, A0, A1, B0, B1);
        if (c + 1 < NC) asm volatile("cp.async.wait_group %0;" :: "n"(1) : "memory");
        else            asm volatile("cp.async.wait_group %0;" :: "n"(0) : "memory");
        __syncthreads();
        const uint32_t sb = base + (c & 1) * STG3;
        const uint32_t Ab = sb, Bb = sb + 2 * ASZ_C;
        {
            const int r16 = lane & 15;
            const int kg  = (lane >> 4) * 16;
            #pragma unroll
            for (int ks = 0; ks < 4; ks++) {
                const int kb = ks * 32 + kg;
                uint32_t af0[4][4], bf0[4][4];
                #pragma unroll
                for (int ms = 0; ms < 4; ms++)
                    LDSM4(af0[ms], Ab + SWZ((wm * 64 + ms * 16 + r16) * 128 + kb));
                #pragma unroll
                for (int nt = 0; nt < 4; nt++)
                    LDSM4(bf0[nt], Bb + SWZ((wn * 64 + nt * 16 + r16) * 128 + kb));
                mmas(acc, af0, bf0);
                uint32_t af1[4][4];
                #pragma unroll
                for (int ms = 0; ms < 4; ms++)
                    LDSM4(af1[ms], Ab + ASZ_C + SWZ((wm * 64 + ms * 16 + r16) * 128 + kb));
                mmas(acc, af1, bf0);
                uint32_t bf1[4][4];
                #pragma unroll
                for (int nt = 0; nt < 4; nt++)
                    LDSM4(bf1[nt], Bb + BSZ_C + SWZ((wn * 64 + nt * 16 + r16) * 128 + kb));
                mmas(acc, af0, bf1);
            }
        }
        __syncthreads();
    }

    #pragma unroll
    for (int ms = 0; ms < 4; ms++) {
        #pragma unroll
        for (int hh = 0; hh < 2; hh++) {
            const int slot = m0 + wm * 64 + ms * 16 + (lane >> 2) + hh * 8;
            const int rg   = rowsm[slot - m0];
            float tc = tcv[rg], ccs = ccv[rg >> 12], tks = tkv[rg >> 12];
            float pc[SUPC];
            #pragma unroll
            for (int ci = 0; ci < SUPC; ci++) pc[ci] = 0.f;
            #pragma unroll
            for (int ns = 0; ns < 8; ns++) {
                #pragma unroll
                for (int e = 0; e < 2; e++) {
                    const int n = n0 + wn * 64 + ns * 8 + (lane & 3) * 2 + e;
                    float v = acc[ms][ns][hh * 2 + e] + bias1[n];
                    v += tc  * W1o[(size_t)2048 * H + n]
                       + ccs * W1o[(size_t)2049 * H + n]
                       + tks * W1o[(size_t)2050 * H + n];
                    float h = gelu_exact(v);
                    #pragma unroll
                    for (int ci = 0; ci < SUPC; ci++)
                        pc[ci] = fmaf(h, W2[(size_t)n * SUPC + ci], pc[ci]);
                }
            }
            #pragma unroll
            for (int ci = 0; ci < SUPC; ci++) {
                pc[ci] += __shfl_xor_sync(0xffffffffu, pc[ci], 1);
                pc[ci] += __shfl_xor_sync(0xffffffffu, pc[ci], 2);
            }
            if ((lane & 3) == 0) {
                #pragma unroll
                for (int ci = 0; ci < SUPC; ci++)
                    atomicAdd(&accout[(size_t)slot * SUPC + ci], pc[ci]);
            }
        }
    }
}

// ---- combined dep GEMM + recheck (single launch -> overlap) ----
__global__ void __launch_bounds__(256, 1)
tc_gemm_dep_re(const __half* __restrict__ X0, const __half* __restrict__ X1,
               const __half* __restrict__ Wd0,
               const __half* __restrict__ Ws0, const __half* __restrict__ Ws1,
               const float* __restrict__ depb1, const float* __restrict__ depW2,
               const float* __restrict__ depW1,
               const float* __restrict__ supb1, const float* __restrict__ supW2,
               const float* __restrict__ supW1,
               float* __restrict__ dlog, float* __restrict__ rlog,
               const float* __restrict__ tcv, const float* __restrict__ ccv,
               const float* __restrict__ tkv)
{
    extern __shared__ char smem[];
    __shared__ int rowsm[128];
    const uint32_t base = smem_to_u32(smem);
    const int bid = blockIdx.x;
    const int tid = threadIdx.x;

    if (bid < RE_BLOCKS) {
        const int m0 = (bid >> 3) * 128;
        const int n0 = (bid & 7) * 256;
        if (m0 >= g_count) return;
        recheck_body(base, m0, n0, tid, rowsm, X0, X1, Ws0, Ws1,
                     supb1, supW2, supW1, rlog, tcv, ccv, tkv);
    } else {
        const int b2 = bid - RE_BLOCKS;
        const int m0 = (b2 >> 3) * 128;
        const int n0 = (b2 & 7) * 256;
        gemm1_body<HEADSC, true>(base, m0, n0, tid, X0, Wd0,
                                 depb1, depW2, depW1, dlog, tcv, ccv, tkv, H);
    }
}

// ================= precompute kernels =================
__global__ void split_x_mean(const float* __restrict__ X) {
    int idx = blockIdx.x * blockDim.x + threadIdx.x;
    int d     = idx & (H - 1);
    int chunk = (idx >> 11) & 15;
    int b     = idx >> 15;
    size_t p = ((size_t)(b * SEQ + chunk * 256)) * H + d;
    float s = 0.f;
    #pragma unroll 4
    for (int t = 0; t < 256; t++) {
        float x = X[p];
        s += x;
        __half h = __float2half_rn(x);
        gX0[p] = h;
        gX1[p] = __float2half_rn(x - __half2float(h));
        p += H;
    }
    atomicAdd(&g_ctxsum[b * H + d], s);
}

// fused transpose of all 4 W1 matrices (blockIdx.z = job)
__global__ void transpose_all(const float* __restrict__ tokW1,
                              const float* __restrict__ effW1,
                              const float* __restrict__ supW1,
                              const float* __restrict__ depW1,
                              __half* __restrict__ o_tok, __half* __restrict__ o_eff,
                              __half* __restrict__ o_sup0, __half* __restrict__ o_sup1,
                              __half* __restrict__ o_dep)
{
    __shared__ float t[32][33];
    const int job = blockIdx.z;
    const float* W; int N; int nsplit; __half *o0, *o1;
    if      (job == 0) { W = tokW1; N = HH; nsplit = 1; o0 = o_tok;  o1 = o_tok;  }
    else if (job == 1) { W = effW1; N = HH; nsplit = 1; o0 = o_eff;  o1 = o_eff;  }
    else if (job == 2) { W = supW1; N = H;  nsplit = 2; o0 = o_sup0; o1 = o_sup1; }
    else               { W = depW1; N = H;  nsplit = 1; o0 = o_dep;  o1 = o_dep;  }

    int n0 = blockIdx.x * 32, k0 = blockIdx.y * 32;
    if (n0 >= N) return;
    int tx = threadIdx.x & 31, ty = threadIdx.x >> 5;
    #pragma unroll
    for (int s = 0; s < 32; s += 8)
        t[ty + s][tx] = W[(size_t)(k0 + ty + s) * N + n0 + tx];
    __syncthreads();
    #pragma unroll
    for (int s = 0; s < 32; s += 8) {
        int n = n0 + ty + s, k = k0 + tx;
        float x = t[tx][ty + s];
        __half hh = __float2half_rn(x);
        o0[(size_t)n * H + k] = hh;
        if (nsplit == 2) {
            float r = x - __half2float(hh);
            o1[(size_t)n * H + k] = __float2half_rn(r);
        }
    }
}

__global__ void zero_scratch() {
    int i = blockIdx.x * blockDim.x + threadIdx.x;
    if (i == 0)               g_count = 0;
    if (i < BATCH * H)        g_ctxsum[i] = 0.f;
    if (i < 8 * HH)           (&g_hid[0][0])[i] = 0.f;
    if (i < M_ROWS)         { g_rowsum0[i] = 0.f; g_rowsum1[i] = 0.f; g_rowmap[i] = 0; }
    if (i < M_ROWS * SUPC)  { g_slog[i] = 0.f; g_rlog[i] = 0.f; }
    if (i < M_ROWS * HEADSC)  g_dlog[i] = 0.f;
}

// ---- ctx/task MLP, chip-wide: partial k-chunks then finalize ----
// grid (32 k-chunks, 8 jobs), 1024 threads = hidden units
__global__ void ctx_task_partial(
    const float* __restrict__ cW1, const float* __restrict__ tW1)
{
    __shared__ float embs[64];
    const int k0  = blockIdx.x * 64;
    const int job = blockIdx.y;          // b = job&3, which = job>>2
    const int b     = job & 3;
    const int which = job >> 2;
    const float* W1 = which ? tW1 : cW1;
    const int tid = threadIdx.x;

    if (tid < 64) embs[tid] = g_ctxsum[b * H + k0 + tid] * (1.0f / SEQ);
    __syncthreads();

    float p = 0.f;
    #pragma unroll
    for (int kk = 0; kk < 64; kk++)
        p = fmaf(embs[kk], W1[(size_t)(k0 + kk) * HH + tid], p);
    atomicAdd(&g_hid[job][tid], p);
}

// grid 8 jobs, 1024 threads
__global__ void ctx_task_final(
    const float* __restrict__ cb1, const float* __restrict__ cW2,
    const float* __restrict__ cb2,
    const float* __restrict__ tb1, const float* __restrict__ tW2,
    const float* __restrict__ tb2,
    float* __restrict__ out)
{
    __shared__ float red[1024];
    const int job = blockIdx.x;
    const int b     = job & 3;
    const int which = job >> 2;
    const float* b1 = which ? tb1 : cb1;
    const float* W2 = which ? tW2 : cW2;
    const float* b2 = which ? tb2 : cb2;
    const int tid = threadIdx.x;

    float a = g_hid[job][tid] + b1[tid];
    red[tid] = gelu_exact(a) * W2[tid];
    __syncthreads();
    for (int off = 512; off > 0; off >>= 1) {
        if (tid < off) red[tid] += red[tid + off];
        __syncthreads();
    }
    if (tid == 0)
        out[(which ? OFF_TASK : OFF_CTX) + b] = sigmoidf_(red[0] + b2[0]);
}

// ================= small finalize kernels =================
__global__ void finalize_tokeff(float* __restrict__ out,
                                const float* __restrict__ tokb2,
                                const float* __restrict__ effb2)
{
    int r = blockIdx.x * blockDim.x + threadIdx.x;
    if (r < M_ROWS) {
        out[OFF_TOK + r] = sigmoidf_(g_rowsum0[r] + tokb2[0]);
        out[OFF_EFF + r] = sigmoidf_(g_rowsum1[r] + effb2[0]);
    }
}

__global__ void softmax_sup_flag(float* __restrict__ out,
                                 const float* __restrict__ supb2)
{
    int r = blockIdx.x * blockDim.x + threadIdx.x;
    if (r >= M_ROWS) return;
    float l[SUPC];
    float m = -1e30f;
    #pragma unroll
    for (int c = 0; c < SUPC; c++) {
        l[c] = g_slog[(size_t)r * SUPC + c] + supb2[c];
        m = fmaxf(m, l[c]);
    }
    float s = 0.f;
    #pragma unroll
    for (int c = 0; c < SUPC; c++) { l[c] = expf(l[c] - m); s += l[c]; }
    float inv = 1.f / s;
    float eff = out[OFF_EFF + r];
    bool flag = false;
    #pragma unroll
    for (int c = 0; c < SUPC; c++) {
        float w = l[c] * inv;
        if (fabsf(w - 0.2f) < RECHECK_MARGIN) flag = true;
        out[OFF_SUP  + (size_t)r * SUPC + c] = w;
        out[OFF_MASK + (size_t)r * SUPC + c] = (w > 0.2f) ? eff : 0.f;
    }
    if (flag) {
        int slot = atomicAdd(&g_count, 1);
        if (slot < M_ROWS) g_rowmap[slot] = r;
    }
}

__global__ void softmax_dep_refinal(float* __restrict__ out,
                                    const float* __restrict__ depb2,
                                    const float* __restrict__ supb2)
{
    int r = blockIdx.x * blockDim.x + threadIdx.x;
    if (r >= M_ROWS) return;
    {
        float l[HEADSC];
        float m = -1e30f;
        #pragma unroll
        for (int c = 0; c < HEADSC; c++) {
            l[c] = g_dlog[(size_t)r * HEADSC + c] + depb2[c];
            m = fmaxf(m, l[c]);
        }
        float s = 0.f;
        #pragma unroll
        for (int c = 0; c < HEADSC; c++) { l[c] = expf(l[c] - m); s += l[c]; }
        float inv = 1.f / s;
        #pragma unroll
        for (int c = 0; c < HEADSC; c++)
            out[OFF_DEP + (size_t)r * HEADSC + c] = l[c] * inv;
    }
    int t = r;
    if (t < g_count && t < RE_MAX_ROWS) {
        int rr = g_rowmap[t];
        float l[SUPC];
        float m = -1e30f;
        #pragma unroll
        for (int c = 0; c < SUPC; c++) {
            l[c] = g_rlog[(size_t)t * SUPC + c] + supb2[c];
            m = fmaxf(m, l[c]);
        }
        float s = 0.f;
        #pragma unroll
        for (int c = 0; c < SUPC; c++) { l[c] = expf(l[c] - m); s += l[c]; }
        float inv = 1.f / s;
        float eff = out[OFF_EFF + rr];
        #pragma unroll
        for (int c = 0; c < SUPC; c++) {
            float w = l[c] * inv;
            out[OFF_SUP  + (size_t)rr * SUPC + c] = w;
            out[OFF_MASK + (size_t)rr * SUPC + c] = (w > 0.2f) ? eff : 0.f;
        }
    }
}

// ================= launch =================
extern "C" void kernel_launch(void* const* d_in, const int* in_sizes, int n_in,
                              void* d_out, int out_size)
{
    const float* X      = (const float*)d_in[0];
    const float* tokW1  = (const float*)d_in[1];
    const float* tokb1  = (const float*)d_in[2];
    const float* tokW2  = (const float*)d_in[3];
    const float* tokb2  = (const float*)d_in[4];
    const float* ctxW1  = (const float*)d_in[5];
    const float* ctxb1  = (const float*)d_in[6];
    const float* ctxW2  = (const float*)d_in[7];
    const float* ctxb2  = (const float*)d_in[8];
    const float* taskW1 = (const float*)d_in[9];
    const float* taskb1 = (const float*)d_in[10];
    const float* taskW2 = (const float*)d_in[11];
    const float* taskb2 = (const float*)d_in[12];
    const float* effW1  = (const float*)d_in[13];
    const float* effb1  = (const float*)d_in[14];
    const float* effW2  = (const float*)d_in[15];
    const float* effb2  = (const float*)d_in[16];
    const float* supW1  = (const float*)d_in[17];
    const float* supb1  = (const float*)d_in[18];
    const float* supW2  = (const float*)d_in[19];
    const float* supb2  = (const float*)d_in[20];
    const float* depW1  = (const float*)d_in[21];
    const float* depb1  = (const float*)d_in[22];
    const float* depW2  = (const float*)d_in[23];
    const float* depb2  = (const float*)d_in[24];
    float* out = (float*)d_out;

    void *pX0, *pX1, *pWt0, *pWe0, *pWs0, *pWs1, *pWd0;
    void *pR0, *pR1, *pSL, *pDL, *pRL;
    cudaGetSymbolAddress(&pX0, gX0);   cudaGetSymbolAddress(&pX1, gX1);
    cudaGetSymbolAddress(&pWt0, gWtok0);
    cudaGetSymbolAddress(&pWe0, gWeff0);
    cudaGetSymbolAddress(&pWs0, gWsup0); cudaGetSymbolAddress(&pWs1, gWsup1);
    cudaGetSymbolAddress(&pWd0, gWdep0);
    cudaGetSymbolAddress(&pR0, g_rowsum0); cudaGetSymbolAddress(&pR1, g_rowsum1);
    cudaGetSymbolAddress(&pSL, g_slog);    cudaGetSymbolAddress(&pDL, g_dlog);
    cudaGetSymbolAddress(&pRL, g_rlog);

    cudaFuncSetAttribute(tc_gemm_tokeff,
                         cudaFuncAttributeMaxDynamicSharedMemorySize, SM1);
    cudaFuncSetAttribute(tc_gemm1<SUPC, true>,
                         cudaFuncAttributeMaxDynamicSharedMemorySize, SM1);
    cudaFuncSetAttribute(tc_gemm_dep_re,
                         cudaFuncAttributeMaxDynamicSharedMemorySize, SM_CMB);

    zero_scratch<<<512, 256>>>();
    split_x_mean<<<512, 256>>>(X);
    transpose_all<<<dim3(H / 32, H / 32, 4), 256>>>(
        tokW1, effW1, supW1, depW1,
        (__half*)pWt0, (__half*)pWe0, (__half*)pWs0, (__half*)pWs1, (__half*)pWd0);

    // ctx/task MLP: chip-wide partials + tiny finalize
    ctx_task_partial<<<dim3(H / 64, 8), 1024>>>(ctxW1, taskW1);
    ctx_task_final<<<8, 1024>>>(ctxb1, ctxW2, ctxb2, taskb1, taskW2, taskb2, out);

    // fused tok + eff GEMM (one launch, compile-time body, pointer dispatch)
    tc_gemm_tokeff<<<dim3(8, M_ROWS / 128), 256, SM1>>>(
        (const __half*)pX0, (const __half*)pWt0, (const __half*)pWe0,
        tokb1, tokW2, effb1, effW2, (float*)pR0, (float*)pR1);
    finalize_tokeff<<<M_ROWS / 256, 256>>>(out, tokb2, effb2);

    // sup: single-pass fp16 with extra features
    tc_gemm1<SUPC, true><<<dim3(H / 256, M_ROWS / 128), 256, SM1>>>(
        (const __half*)pX0, (const __half*)pWs0,
        supb1, supW2, supW1, (float*)pSL,
        out + OFF_TOK, out + OFF_CTX, out + OFF_TASK, H);

    softmax_sup_flag<<<M_ROWS / 256, 256>>>(out, supb2);

    // combined: recheck blocks (first wave) + dep GEMM blocks — overlapped
    tc_gemm_dep_re<<<RE_BLOCKS + 8 * (M_ROWS / 128), 256, SM_CMB>>>(
        (const __half*)pX0, (const __half*)pX1, (const __half*)pWd0,
        (const __half*)pWs0, (const __half*)pWs1,
        depb1, depW2, depW1, supb1, supW2, supW1,
        (float*)pDL, (float*)pRL,
        out + OFF_TOK, out + OFF_CTX, out + OFF_TASK);

    softmax_dep_refinal<<<M_ROWS / 256, 256>>>(out, depb2, supb2);

    (void)in_sizes; (void)n_in; (void)out_size;
}

// round 15
// speedup vs baseline: 1.2601x; 1.0043x over previous
#include <cuda_runtime.h>
#include <cuda_fp16.h>
#include <cstdint>
#include <math.h>

#define H      2048
#define HH     1024
#define BATCH  4
#define SEQ    4096
#define M_ROWS 16384
#define SUPC   4
#define HEADSC 8

// d_out float offsets (tuple order, flattened)
#define OFF_TOK  0
#define OFF_CTX  16384
#define OFF_TASK 16388
#define OFF_SUP  16392
#define OFF_DEP  81928
#define OFF_EFF  213000
#define OFF_MASK 229384

#define RECHECK_MARGIN 0.005f
#define RE_MAX_ROWS    4096
#define RE_BLOCKS      256       // 32 m-blocks x 8 n-blocks

// ================= scratch (no allocations allowed) =================
__device__ float g_ctxsum[BATCH * H];
__device__ float g_hid[8][HH];           // ctx/task hidden partials
__device__ float g_rowsum0[M_ROWS];
__device__ float g_rowsum1[M_ROWS];
__device__ float g_slog[M_ROWS * SUPC];
__device__ float g_dlog[M_ROWS * HEADSC];
__device__ int   g_count;
__device__ int   g_rowmap[M_ROWS];
__device__ float g_rlog[M_ROWS * SUPC];

__device__ __half gX0[M_ROWS * H];
__device__ __half gX1[M_ROWS * H];       // filled lazily (flagged rows only)
__device__ __half gWtok0[HH * H];
__device__ __half gWeff0[HH * H];
__device__ __half gWsup0[H * H];
__device__ __half gWsup1[H * H];
__device__ __half gWdep0[H * H];

__device__ __forceinline__ float gelu_exact(float x) {
    return 0.5f * x * (1.0f + erff(x * 0.70710678118654752f));
}
__device__ __forceinline__ float sigmoidf_(float x) {
    return 1.0f / (1.0f + expf(-x));
}
__device__ __forceinline__ uint32_t smem_to_u32(const void* p) {
    uint32_t a;
    asm("{ .reg .u64 t; cvta.to.shared.u64 t, %1; cvt.u32.u64 %0, t; }" : "=r"(a) : "l"(p));
    return a;
}
#define SWZ(off) ((off) ^ (((off) >> 3) & 0x70))

#define LDSM4(r, addr) \
    asm volatile("ldmatrix.sync.aligned.m8n8.x4.shared.b16 {%0,%1,%2,%3}, [%4];" \
                 : "=r"((r)[0]), "=r"((r)[1]), "=r"((r)[2]), "=r"((r)[3]) : "r"(addr))

static constexpr int ASZ_C = 128 * 128;   // 16KB: A tile (128 rows x 64 fp16)
static constexpr int BSZ_C = 256 * 128;   // 32KB: B tile (256 rows x 64 fp16)
static constexpr int STG1  = ASZ_C + BSZ_C;   // 48KB stage
static constexpr int SM1   = 3 * STG1;        // 147456
static constexpr int STG3  = 2 * STG1;        // 96KB (recheck: 2 parts)
static constexpr int SM_CMB = 2 * STG3;       // 196608

// ---- 8 warps, warp grid 2(m) x 4(n), warp tile 64x64 ----
__device__ __forceinline__ void mmas(float (&acc)[4][8][4],
                                     uint32_t (&a)[4][4], uint32_t (&b)[4][4]) {
    #pragma unroll
    for (int ms = 0; ms < 4; ms++)
        #pragma unroll
        for (int ns = 0; ns < 8; ns++) {
            uint32_t b0 = b[ns >> 1][ns & 1];
            uint32_t b1 = b[ns >> 1][2 + (ns & 1)];
            asm volatile(
                "mma.sync.aligned.m16n8k16.row.col.f32.f16.f16.f32 "
                "{%0,%1,%2,%3}, {%4,%5,%6,%7}, {%8,%9}, {%0,%1,%2,%3};"
                : "+f"(acc[ms][ns][0]), "+f"(acc[ms][ns][1]),
                  "+f"(acc[ms][ns][2]), "+f"(acc[ms][ns][3])
                : "r"(a[ms][0]), "r"(a[ms][1]), "r"(a[ms][2]), "r"(a[ms][3]),
                  "r"(b0), "r"(b1));
        }
}

__device__ __forceinline__ void ldfrag(uint32_t Ab, uint32_t Bb, int wm, int wn,
                                       int r16, int kb,
                                       uint32_t (&a)[4][4], uint32_t (&b)[4][4]) {
    #pragma unroll
    for (int ms = 0; ms < 4; ms++)
        LDSM4(a[ms], Ab + SWZ((wm * 64 + ms * 16 + r16) * 128 + kb));
    #pragma unroll
    for (int nt = 0; nt < 4; nt++)
        LDSM4(b[nt], Bb + SWZ((wn * 64 + nt * 16 + r16) * 128 + kb));
}

__device__ __forceinline__ void compute_chunk1(uint32_t Ab, uint32_t Bb,
        float (&acc)[4][8][4], int wm, int wn, int lane) {
    const int r16 = lane & 15;
    const int kg  = (lane >> 4) * 16;
    #pragma unroll
    for (int ks = 0; ks < 4; ks++) {
        const int kb = ks * 32 + kg;
        uint32_t a[4][4], b[4][4];
        ldfrag(Ab, Bb, wm, wn, r16, kb, a, b);
        mmas(acc, a, b);
    }
}

// ---- loaders ----
__device__ __forceinline__ void load1(uint32_t dstbase, int kc, int m0, int n0,
                                      int tid, const __half* __restrict__ A0,
                                      const __half* __restrict__ B0) {
    for (int idx = tid; idx < 3072; idx += 256) {
        uint32_t dst;
        const __half* src;
        if (idx < 1024) {
            int r = idx >> 3, i = idx & 7;
            dst = dstbase + SWZ(r * 128 + i * 16);
            src = A0 + (size_t)(m0 + r) * H + kc * 64 + i * 8;
        } else {
            int j = idx - 1024;
            int r = j >> 3, i = j & 7;
            dst = dstbase + ASZ_C + SWZ(r * 128 + i * 16);
            src = B0 + (size_t)(n0 + r) * H + kc * 64 + i * 8;
        }
        asm volatile("cp.async.cg.shared.global [%0], [%1], 16;" :: "r"(dst), "l"(src) : "memory");
    }
    asm volatile("cp.async.commit_group;" ::: "memory");
}

__device__ __forceinline__ void load3(uint32_t dstbase, int kc, int tid,
                                      const int* rs, int n0,
                                      const __half* __restrict__ A0,
                                      const __half* __restrict__ A1,
                                      const __half* __restrict__ B0,
                                      const __half* __restrict__ B1) {
    for (int idx = tid; idx < 2048 + 4096; idx += 256) {
        uint32_t dst;
        const __half* src;
        if (idx < 2048) {
            int s = idx >> 10;
            int r = (idx & 1023) >> 3;
            int i = idx & 7;
            dst = dstbase + s * ASZ_C + SWZ(r * 128 + i * 16);
            src = (s ? A1 : A0) + (size_t)rs[r] * H + kc * 64 + i * 8;
        } else {
            int j = idx - 2048;
            int s = j >> 11;
            int r = (j & 2047) >> 3;
            int i = j & 7;
            dst = dstbase + 2 * ASZ_C + s * BSZ_C + SWZ(r * 128 + i * 16);
            src = (s ? B1 : B0) + (size_t)(n0 + r) * H + kc * 64 + i * 8;
        }
        asm volatile("cp.async.cg.shared.global [%0], [%1], 16;" :: "r"(dst), "l"(src) : "memory");
    }
    asm volatile("cp.async.commit_group;" ::: "memory");
}

// ---- single-pass GEMM body (compile-time C/EX), 256 threads ----
// one-sync mainloop: wait -> sync -> issue load(c+2) -> compute(c).
// The single sync proves all warps finished compute(c-1), whose buffer
// (c-1)%3 == (c+2)%3 is exactly what the new load overwrites.
template <int C, bool EX>
__device__ __forceinline__ void gemm1_body(
    uint32_t base, int m0, int n0, int tid,
    const __half* __restrict__ A0, const __half* __restrict__ B0,
    const float* __restrict__ bias1, const float* __restrict__ W2,
    const float* __restrict__ W1o, float* __restrict__ accout,
    const float* __restrict__ tcv, const float* __restrict__ ccv,
    const float* __restrict__ tkv, int Ntot)
{
    constexpr int NC = H / 64;
    const int lane = tid & 31;
    const int wid  = tid >> 5;
    const int wm   = wid >> 2;
    const int wn   = wid & 3;

    float acc[4][8][4];
    #pragma unroll
    for (int a = 0; a < 4; a++)
        #pragma unroll
        for (int b = 0; b < 8; b++)
            #pragma unroll
            for (int c = 0; c < 4; c++) acc[a][b][c] = 0.f;

    load1(base + 0 * STG1, 0, m0, n0, tid, A0, B0);
    load1(base + 1 * STG1, 1, m0, n0, tid, A0, B0);

    for (int c = 0; c < NC; c++) {
        if (c + 1 < NC) asm volatile("cp.async.wait_group %0;" :: "n"(1) : "memory");
        else            asm volatile("cp.async.wait_group %0;" :: "n"(0) : "memory");
        __syncthreads();
        if (c + 2 < NC)
            load1(base + ((c + 2) % 3) * STG1, c + 2, m0, n0, tid, A0, B0);
        const uint32_t sb = base + (c % 3) * STG1;
        compute_chunk1(sb, sb + ASZ_C, acc, wm, wn, lane);
    }

    float ccs = 0.f, tks = 0.f;
    if (EX) { ccs = ccv[m0 >> 12]; tks = tkv[m0 >> 12]; }

    #pragma unroll
    for (int ms = 0; ms < 4; ms++) {
        #pragma unroll
        for (int hh = 0; hh < 2; hh++) {
            const int r = m0 + wm * 64 + ms * 16 + (lane >> 2) + hh * 8;
            float tc = 0.f;
            if (EX) tc = tcv[r];
            float pc[C];
            #pragma unroll
            for (int ci = 0; ci < C; ci++) pc[ci] = 0.f;
            #pragma unroll
            for (int ns = 0; ns < 8; ns++) {
                #pragma unroll
                for (int e = 0; e < 2; e++) {
                    const int n = n0 + wn * 64 + ns * 8 + (lane & 3) * 2 + e;
                    float v = acc[ms][ns][hh * 2 + e] + bias1[n];
                    if (EX) {
                        v += tc  * W1o[(size_t)2048 * Ntot + n]
                           + ccs * W1o[(size_t)2049 * Ntot + n]
                           + tks * W1o[(size_t)2050 * Ntot + n];
                    }
                    float h = gelu_exact(v);
                    #pragma unroll
                    for (int ci = 0; ci < C; ci++)
                        pc[ci] = fmaf(h, W2[(size_t)n * C + ci], pc[ci]);
                }
            }
            #pragma unroll
            for (int ci = 0; ci < C; ci++) {
                pc[ci] += __shfl_xor_sync(0xffffffffu, pc[ci], 1);
                pc[ci] += __shfl_xor_sync(0xffffffffu, pc[ci], 2);
            }
            if ((lane & 3) == 0) {
                #pragma unroll
                for (int ci = 0; ci < C; ci++)
                    atomicAdd(&accout[(size_t)r * C + ci], pc[ci]);
            }
        }
    }
}

// ---- fused tok+eff GEMM: bid-dispatch, same compile-time body ----
__global__ void __launch_bounds__(256, 1)
tc_gemm_tokeff(const __half* __restrict__ X0,
               const __half* __restrict__ Wt0, const __half* __restrict__ We0,
               const float* __restrict__ tokb1, const float* __restrict__ tokW2,
               const float* __restrict__ effb1, const float* __restrict__ effW2,
               float* __restrict__ r0, float* __restrict__ r1)
{
    extern __shared__ char smem[];
    const int seg = blockIdx.x >> 2;
    const int n0  = (blockIdx.x & 3) * 256;
    gemm1_body<1, false>(smem_to_u32(smem), blockIdx.y * 128, n0, threadIdx.x,
                         X0, seg ? We0 : Wt0,
                         seg ? effb1 : tokb1, seg ? effW2 : tokW2,
                         nullptr, seg ? r1 : r0, nullptr, nullptr, nullptr, HH);
}

// ---- sup GEMM ----
template <int C, bool EX>
__global__ void __launch_bounds__(256, 1)
tc_gemm1(const __half* __restrict__ A0, const __half* __restrict__ B0,
         const float* __restrict__ bias1, const float* __restrict__ W2,
         const float* __restrict__ W1o, float* __restrict__ accout,
         const float* __restrict__ tcv, const float* __restrict__ ccv,
         const float* __restrict__ tkv, int Ntot)
{
    extern __shared__ char smem[];
    gemm1_body<C, EX>(smem_to_u32(smem), blockIdx.y * 128, blockIdx.x * 256,
                      threadIdx.x, A0, B0, bias1, W2, W1o, accout, tcv, ccv, tkv, Ntot);
}

// ---- gathered 3-term recheck body (unchanged, measured-good) ----
__device__ __forceinline__ void recheck_body(
    uint32_t base, int m0, int n0, int tid, int* rowsm,
    const __half* __restrict__ A0, const __half* __restrict__ A1,
    const __half* __restrict__ B0, const __half* __restrict__ B1,
    const float* __restrict__ bias1, const float* __restrict__ W2,
    const float* __restrict__ W1o, float* __restrict__ accout,
    const float* __restrict__ tcv, const float* __restrict__ ccv,
    const float* __restrict__ tkv)
{
    constexpr int NC = H / 64;
    const int lane = tid & 31;
    const int wid  = tid >> 5;
    const int wm   = wid >> 2;
    const int wn   = wid & 3;

    for (int i = tid; i < 128; i += 256) rowsm[i] = g_rowmap[m0 + i];
    __syncthreads();

    float acc[4][8][4];
    #pragma unroll
    for (int a = 0; a < 4; a++)
        #pragma unroll
        for (int b = 0; b < 8; b++)
            #pragma unroll
            for (int c = 0; c < 4; c++) acc[a][b][c] = 0.f;

    load3(base, 0, tid, rowsm, n0, A0, A1, B0, B1);

    for (int c = 0; c < NC; c++) {
        if (c + 1 < NC)
            load3(base + ((c + 1) & 1) * STG3, c + 1, tid, rowsm, n0, A0, A1, B0, B1);
        if (c + 1 < NC) asm volatile("cp.async.wait_group %0;" :: "n"(1) : "memory");
        else            asm volatile("cp.async.wait_group %0;" :: "n"(0) : "memory");
        __syncthreads();
        const uint32_t sb = base + (c & 1) * STG3;
        const uint32_t Ab = sb, Bb = sb + 2 * ASZ_C;
        {
            const int r16 = lane & 15;
            const int kg  = (lane >> 4) * 16;
            #pragma unroll
            for (int ks = 0; ks < 4; ks++) {
                const int kb = ks * 32 + kg;
                uint32_t af0[4][4], bf0[4][4];
                #pragma unroll
                for (int ms = 0; ms < 4; ms++)
                    LDSM4(af0[ms], Ab + SWZ((wm * 64 + ms * 16 + r16) * 128 + kb));
                #pragma unroll
                for (int nt = 0; nt < 4; nt++)
                    LDSM4(bf0[nt], Bb + SWZ((wn * 64 + nt * 16 + r16) * 128 + kb));
                mmas(acc, af0, bf0);
                uint32_t af1[4][4];
                #pragma unroll
                for (int ms = 0; ms < 4; ms++)
                    LDSM4(af1[ms], Ab + ASZ_C + SWZ((wm * 64 + ms * 16 + r16) * 128 + kb));
                mmas(acc, af1, bf0);
                uint32_t bf1[4][4];
                #pragma unroll
                for (int nt = 0; nt < 4; nt++)
                    LDSM4(bf1[nt], Bb + BSZ_C + SWZ((wn * 64 + nt * 16 + r16) * 128 + kb));
                mmas(acc, af0, bf1);
            }
        }
        __syncthreads();
    }

    #pragma unroll
    for (int ms = 0; ms < 4; ms++) {
        #pragma unroll
        for (int hh = 0; hh < 2; hh++) {
            const int slot = m0 + wm * 64 + ms * 16 + (lane >> 2) + hh * 8;
            const int rg   = rowsm[slot - m0];
            float tc = tcv[rg], ccs = ccv[rg >> 12], tks = tkv[rg >> 12];
            float pc[SUPC];
            #pragma unroll
            for (int ci = 0; ci < SUPC; ci++) pc[ci] = 0.f;
            #pragma unroll
            for (int ns = 0; ns < 8; ns++) {
                #pragma unroll
                for (int e = 0; e < 2; e++) {
                    const int n = n0 + wn * 64 + ns * 8 + (lane & 3) * 2 + e;
                    float v = acc[ms][ns][hh * 2 + e] + bias1[n];
                    v += tc  * W1o[(size_t)2048 * H + n]
                       + ccs * W1o[(size_t)2049 * H + n]
                       + tks * W1o[(size_t)2050 * H + n];
                    float h = gelu_exact(v);
                    #pragma unroll
                    for (int ci = 0; ci < SUPC; ci++)
                        pc[ci] = fmaf(h, W2[(size_t)n * SUPC + ci], pc[ci]);
                }
            }
            #pragma unroll
            for (int ci = 0; ci < SUPC; ci++) {
                pc[ci] += __shfl_xor_sync(0xffffffffu, pc[ci], 1);
                pc[ci] += __shfl_xor_sync(0xffffffffu, pc[ci], 2);
            }
            if ((lane & 3) == 0) {
                #pragma unroll
                for (int ci = 0; ci < SUPC; ci++)
                    atomicAdd(&accout[(size_t)slot * SUPC + ci], pc[ci]);
            }
        }
    }
}

// ---- combined dep GEMM + recheck (single launch -> overlap) ----
__global__ void __launch_bounds__(256, 1)
tc_gemm_dep_re(const __half* __restrict__ X0, const __half* __restrict__ X1,
               const __half* __restrict__ Wd0,
               const __half* __restrict__ Ws0, const __half* __restrict__ Ws1,
               const float* __restrict__ depb1, const float* __restrict__ depW2,
               const float* __restrict__ depW1,
               const float* __restrict__ supb1, const float* __restrict__ supW2,
               const float* __restrict__ supW1,
               float* __restrict__ dlog, float* __restrict__ rlog,
               const float* __restrict__ tcv, const float* __restrict__ ccv,
               const float* __restrict__ tkv)
{
    extern __shared__ char smem[];
    __shared__ int rowsm[128];
    const uint32_t base = smem_to_u32(smem);
    const int bid = blockIdx.x;
    const int tid = threadIdx.x;

    if (bid < RE_BLOCKS) {
        const int m0 = (bid >> 3) * 128;
        const int n0 = (bid & 7) * 256;
        if (m0 >= g_count) return;
        recheck_body(base, m0, n0, tid, rowsm, X0, X1, Ws0, Ws1,
                     supb1, supW2, supW1, rlog, tcv, ccv, tkv);
    } else {
        const int b2 = bid - RE_BLOCKS;
        const int m0 = (b2 >> 3) * 128;
        const int n0 = (b2 & 7) * 256;
        gemm1_body<HEADSC, true>(base, m0, n0, tid, X0, Wd0,
                                 depb1, depW2, depW1, dlog, tcv, ccv, tkv, H);
    }
}

// ================= precompute kernels =================
// split X (hi part only) + column sums for the mean
__global__ void split_x_mean(const float* __restrict__ X) {
    int idx = blockIdx.x * blockDim.x + threadIdx.x;
    int d     = idx & (H - 1);
    int chunk = (idx >> 11) & 15;
    int b     = idx >> 15;
    size_t p = ((size_t)(b * SEQ + chunk * 256)) * H + d;
    float s = 0.f;
    #pragma unroll 4
    for (int t = 0; t < 256; t++) {
        float x = X[p];
        s += x;
        gX0[p] = __float2half_rn(x);
        p += H;
    }
    atomicAdd(&g_ctxsum[b * H + d], s);
}

// lazy residual split: only for flagged rows (grid RE_MAX_ROWS, early exit)
__global__ void fill_x1_flagged(const float* __restrict__ X) {
    const int slot = blockIdx.x;
    if (slot >= g_count || slot >= RE_MAX_ROWS) return;
    const int row = g_rowmap[slot];
    const int tid = threadIdx.x;   // 256 threads, 8 elems each
    #pragma unroll
    for (int i = 0; i < 8; i++) {
        size_t p = (size_t)row * H + tid * 8 + i;
        float x = X[p];
        __half h = __float2half_rn(x);
        gX1[p] = __float2half_rn(x - __half2float(h));
    }
}

// fused transpose of all 4 W1 matrices (blockIdx.z = job)
__global__ void transpose_all(const float* __restrict__ tokW1,
                              const float* __restrict__ effW1,
                              const float* __restrict__ supW1,
                              const float* __restrict__ depW1,
                              __half* __restrict__ o_tok, __half* __restrict__ o_eff,
                              __half* __restrict__ o_sup0, __half* __restrict__ o_sup1,
                              __half* __restrict__ o_dep)
{
    __shared__ float t[32][33];
    const int job = blockIdx.z;
    const float* W; int N; int nsplit; __half *o0, *o1;
    if      (job == 0) { W = tokW1; N = HH; nsplit = 1; o0 = o_tok;  o1 = o_tok;  }
    else if (job == 1) { W = effW1; N = HH; nsplit = 1; o0 = o_eff;  o1 = o_eff;  }
    else if (job == 2) { W = supW1; N = H;  nsplit = 2; o0 = o_sup0; o1 = o_sup1; }
    else               { W = depW1; N = H;  nsplit = 1; o0 = o_dep;  o1 = o_dep;  }

    int n0 = blockIdx.x * 32, k0 = blockIdx.y * 32;
    if (n0 >= N) return;
    int tx = threadIdx.x & 31, ty = threadIdx.x >> 5;
    #pragma unroll
    for (int s = 0; s < 32; s += 8)
        t[ty + s][tx] = W[(size_t)(k0 + ty + s) * N + n0 + tx];
    __syncthreads();
    #pragma unroll
    for (int s = 0; s < 32; s += 8) {
        int n = n0 + ty + s, k = k0 + tx;
        float x = t[tx][ty + s];
        __half hh = __float2half_rn(x);
        o0[(size_t)n * H + k] = hh;
        if (nsplit == 2) {
            float r = x - __half2float(hh);
            o1[(size_t)n * H + k] = __float2half_rn(r);
        }
    }
}

__global__ void zero_scratch() {
    int i = blockIdx.x * blockDim.x + threadIdx.x;
    if (i == 0)               g_count = 0;
    if (i < BATCH * H)        g_ctxsum[i] = 0.f;
    if (i < 8 * HH)           (&g_hid[0][0])[i] = 0.f;
    if (i < M_ROWS)         { g_rowsum0[i] = 0.f; g_rowsum1[i] = 0.f; g_rowmap[i] = 0; }
    if (i < M_ROWS * SUPC)  { g_slog[i] = 0.f; g_rlog[i] = 0.f; }
    if (i < M_ROWS * HEADSC)  g_dlog[i] = 0.f;
}

// ---- ctx/task MLP, chip-wide: partial k-chunks then finalize ----
__global__ void ctx_task_partial(
    const float* __restrict__ cW1, const float* __restrict__ tW1)
{
    __shared__ float embs[64];
    const int k0  = blockIdx.x * 64;
    const int job = blockIdx.y;
    const int b     = job & 3;
    const int which = job >> 2;
    const float* W1 = which ? tW1 : cW1;
    const int tid = threadIdx.x;

    if (tid < 64) embs[tid] = g_ctxsum[b * H + k0 + tid] * (1.0f / SEQ);
    __syncthreads();

    float p = 0.f;
    #pragma unroll
    for (int kk = 0; kk < 64; kk++)
        p = fmaf(embs[kk], W1[(size_t)(k0 + kk) * HH + tid], p);
    atomicAdd(&g_hid[job][tid], p);
}

__global__ void ctx_task_final(
    const float* __restrict__ cb1, const float* __restrict__ cW2,
    const float* __restrict__ cb2,
    const float* __restrict__ tb1, const float* __restrict__ tW2,
    const float* __restrict__ tb2,
    float* __restrict__ out)
{
    __shared__ float red[1024];
    const int job = blockIdx.x;
    const int b     = job & 3;
    const int which = job >> 2;
    const float* b1 = which ? tb1 : cb1;
    const float* W2 = which ? tW2 : cW2;
    const float* b2 = which ? tb2 : cb2;
    const int tid = threadIdx.x;

    float a = g_hid[job][tid] + b1[tid];
    red[tid] = gelu_exact(a) * W2[tid];
    __syncthreads();
    for (int off = 512; off > 0; off >>= 1) {
        if (tid < off) red[tid] += red[tid + off];
        __syncthreads();
    }
    if (tid == 0)
        out[(which ? OFF_TASK : OFF_CTX) + b] = sigmoidf_(red[0] + b2[0]);
}

// ================= small finalize kernels =================
__global__ void finalize_tokeff(float* __restrict__ out,
                                const float* __restrict__ tokb2,
                                const float* __restrict__ effb2)
{
    int r = blockIdx.x * blockDim.x + threadIdx.x;
    if (r < M_ROWS) {
        out[OFF_TOK + r] = sigmoidf_(g_rowsum0[r] + tokb2[0]);
        out[OFF_EFF + r] = sigmoidf_(g_rowsum1[r] + effb2[0]);
    }
}

__global__ void softmax_sup_flag(float* __restrict__ out,
                                 const float* __restrict__ supb2)
{
    int r = blockIdx.x * blockDim.x + threadIdx.x;
    if (r >= M_ROWS) return;
    float l[SUPC];
    float m = -1e30f;
    #pragma unroll
    for (int c = 0; c < SUPC; c++) {
        l[c] = g_slog[(size_t)r * SUPC + c] + supb2[c];
        m = fmaxf(m, l[c]);
    }
    float s = 0.f;
    #pragma unroll
    for (int c = 0; c < SUPC; c++) { l[c] = expf(l[c] - m); s += l[c]; }
    float inv = 1.f / s;
    float eff = out[OFF_EFF + r];
    bool flag = false;
    #pragma unroll
    for (int c = 0; c < SUPC; c++) {
        float w = l[c] * inv;
        if (fabsf(w - 0.2f) < RECHECK_MARGIN) flag = true;
        out[OFF_SUP  + (size_t)r * SUPC + c] = w;
        out[OFF_MASK + (size_t)r * SUPC + c] = (w > 0.2f) ? eff : 0.f;
    }
    if (flag) {
        int slot = atomicAdd(&g_count, 1);
        if (slot < M_ROWS) g_rowmap[slot] = r;
    }
}

__global__ void softmax_dep_refinal(float* __restrict__ out,
                                    const float* __restrict__ depb2,
                                    const float* __restrict__ supb2)
{
    int r = blockIdx.x * blockDim.x + threadIdx.x;
    if (r >= M_ROWS) return;
    {
        float l[HEADSC];
        float m = -1e30f;
        #pragma unroll
        for (int c = 0; c < HEADSC; c++) {
            l[c] = g_dlog[(size_t)r * HEADSC + c] + depb2[c];
            m = fmaxf(m, l[c]);
        }
        float s = 0.f;
        #pragma unroll
        for (int c = 0; c < HEADSC; c++) { l[c] = expf(l[c] - m); s += l[c]; }
        float inv = 1.f / s;
        #pragma unroll
        for (int c = 0; c < HEADSC; c++)
            out[OFF_DEP + (size_t)r * HEADSC + c] = l[c] * inv;
    }
    int t = r;
    if (t < g_count && t < RE_MAX_ROWS) {
        int rr = g_rowmap[t];
        float l[SUPC];
        float m = -1e30f;
        #pragma unroll
        for (int c = 0; c < SUPC; c++) {
            l[c] = g_rlog[(size_t)t * SUPC + c] + supb2[c];
            m = fmaxf(m, l[c]);
        }
        float s = 0.f;
        #pragma unroll
        for (int c = 0; c < SUPC; c++) { l[c] = expf(l[c] - m); s += l[c]; }
        float inv = 1.f / s;
        float eff = out[OFF_EFF + rr];
        #pragma unroll
        for (int c = 0; c < SUPC; c++) {
            float w = l[c] * inv;
            out[OFF_SUP  + (size_t)rr * SUPC + c] = w;
            out[OFF_MASK + (size_t)rr * SUPC + c] = (w > 0.2f) ? eff : 0.f;
        }
    }
}

// ================= launch =================
extern "C" void kernel_launch(void* const* d_in, const int* in_sizes, int n_in,
                              void* d_out, int out_size)
{
    const float* X      = (const float*)d_in[0];
    const float* tokW1  = (const float*)d_in[1];
    const float* tokb1  = (const float*)d_in[2];
    const float* tokW2  = (const float*)d_in[3];
    const float* tokb2  = (const float*)d_in[4];
    const float* ctxW1  = (const float*)d_in[5];
    const float* ctxb1  = (const float*)d_in[6];
    const float* ctxW2  = (const float*)d_in[7];
    const float* ctxb2  = (const float*)d_in[8];
    const float* taskW1 = (const float*)d_in[9];
    const float* taskb1 = (const float*)d_in[10];
    const float* taskW2 = (const float*)d_in[11];
    const float* taskb2 = (const float*)d_in[12];
    const float* effW1  = (const float*)d_in[13];
    const float* effb1  = (const float*)d_in[14];
    const float* effW2  = (const float*)d_in[15];
    const float* effb2  = (const float*)d_in[16];
    const float* supW1  = (const float*)d_in[17];
    const float* supb1  = (const float*)d_in[18];
    const float* supW2  = (const float*)d_in[19];
    const float* supb2  = (const float*)d_in[20];
    const float* depW1  = (const float*)d_in[21];
    const float* depb1  = (const float*)d_in[22];
    const float* depW2  = (const float*)d_in[23];
    const float* depb2  = (const float*)d_in[24];
    float* out = (float*)d_out;

    void *pX0, *pX1, *pWt0, *pWe0, *pWs0, *pWs1, *pWd0;
    void *pR0, *pR1, *pSL, *pDL, *pRL;
    cudaGetSymbolAddress(&pX0, gX0);   cudaGetSymbolAddress(&pX1, gX1);
    cudaGetSymbolAddress(&pWt0, gWtok0);
    cudaGetSymbolAddress(&pWe0, gWeff0);
    cudaGetSymbolAddress(&pWs0, gWsup0); cudaGetSymbolAddress(&pWs1, gWsup1);
    cudaGetSymbolAddress(&pWd0, gWdep0);
    cudaGetSymbolAddress(&pR0, g_rowsum0); cudaGetSymbolAddress(&pR1, g_rowsum1);
    cudaGetSymbolAddress(&pSL, g_slog);    cudaGetSymbolAddress(&pDL, g_dlog);
    cudaGetSymbolAddress(&pRL, g_rlog);

    cudaFuncSetAttribute(tc_gemm_tokeff,
                         cudaFuncAttributeMaxDynamicSharedMemorySize, SM1);
    cudaFuncSetAttribute(tc_gemm1<SUPC, true>,
                         cudaFuncAttributeMaxDynamicSharedMemorySize, SM1);
    cudaFuncSetAttribute(tc_gemm_dep_re,
                         cudaFuncAttributeMaxDynamicSharedMemorySize, SM_CMB);

    zero_scratch<<<512, 256>>>();
    split_x_mean<<<512, 256>>>(X);
    transpose_all<<<dim3(H / 32, H / 32, 4), 256>>>(
        tokW1, effW1, supW1, depW1,
        (__half*)pWt0, (__half*)pWe0, (__half*)pWs0, (__half*)pWs1, (__half*)pWd0);

    // ctx/task MLP: chip-wide partials + tiny finalize
    ctx_task_partial<<<dim3(H / 64, 8), 1024>>>(ctxW1, taskW1);
    ctx_task_final<<<8, 1024>>>(ctxb1, ctxW2, ctxb2, taskb1, taskW2, taskb2, out);

    // fused tok + eff GEMM
    tc_gemm_tokeff<<<dim3(8, M_ROWS / 128), 256, SM1>>>(
        (const __half*)pX0, (const __half*)pWt0, (const __half*)pWe0,
        tokb1, tokW2, effb1, effW2, (float*)pR0, (float*)pR1);
    finalize_tokeff<<<M_ROWS / 256, 256>>>(out, tokb2, effb2);

    // sup: single-pass fp16 with extra features
    tc_gemm1<SUPC, true><<<dim3(H / 256, M_ROWS / 128), 256, SM1>>>(
        (const __half*)pX0, (const __half*)pWs0,
        supb1, supW2, supW1, (float*)pSL,
        out + OFF_TOK, out + OFF_CTX, out + OFF_TASK, H);

    softmax_sup_flag<<<M_ROWS / 256, 256>>>(out, supb2);

    // lazy residual split for flagged rows only
    fill_x1_flagged<<<RE_MAX_ROWS, 256>>>(X);

    // combined: recheck blocks (first wave) + dep GEMM blocks — overlapped
    tc_gemm_dep_re<<<RE_BLOCKS + 8 * (M_ROWS / 128), 256, SM_CMB>>>(
        (const __half*)pX0, (const __half*)pX1, (const __half*)pWd0,
        (const __half*)pWs0, (const __half*)pWs1,
        depb1, depW2, depW1, supb1, supW2, supW1,
        (float*)pDL, (float*)pRL,
        out + OFF_TOK, out + OFF_CTX, out + OFF_TASK);

    softmax_dep_refinal<<<M_ROWS / 256, 256>>>(out, depb2, supb2);

    (void)in_sizes; (void)n_in; (void)out_size;
}

// round 16
// speedup vs baseline: 1.2614x; 1.0010x over previous
#include <cuda_runtime.h>
#include <cuda_fp16.h>
#include <cstdint>
#include <math.h>

#define H      2048
#define HH     1024
#define BATCH  4
#define SEQ    4096
#define M_ROWS 16384
#define SUPC   4
#define HEADSC 8

// d_out float offsets (tuple order, flattened)
#define OFF_TOK  0
#define OFF_CTX  16384
#define OFF_TASK 16388
#define OFF_SUP  16392
#define OFF_DEP  81928
#define OFF_EFF  213000
#define OFF_MASK 229384

#define RECHECK_MARGIN 0.005f
#define RE_MAX_ROWS    4096
#define RE_BLOCKS      256       // 32 m-blocks x 8 n-blocks

// ================= scratch (no allocations allowed) =================
__device__ float g_ctxsum[BATCH * H];
__device__ float g_hid[8][HH];           // ctx/task hidden partials
__device__ float g_rowsum0[M_ROWS];
__device__ float g_rowsum1[M_ROWS];
__device__ float g_slog[M_ROWS * SUPC];
__device__ float g_dlog[M_ROWS * HEADSC];
__device__ int   g_count;
__device__ int   g_rowmap[M_ROWS];
__device__ float g_rlog[M_ROWS * SUPC];

__device__ __half gX0[M_ROWS * H];
__device__ __half gX1[M_ROWS * H];       // filled lazily (flagged rows only)
__device__ __half gWtok0[HH * H];
__device__ __half gWeff0[HH * H];
__device__ __half gWsup0[H * H];
__device__ __half gWsup1[H * H];
__device__ __half gWdep0[H * H];

__device__ __forceinline__ float gelu_exact(float x) {
    return 0.5f * x * (1.0f + erff(x * 0.70710678118654752f));
}
__device__ __forceinline__ float sigmoidf_(float x) {
    return 1.0f / (1.0f + expf(-x));
}
__device__ __forceinline__ uint32_t smem_to_u32(const void* p) {
    uint32_t a;
    asm("{ .reg .u64 t; cvta.to.shared.u64 t, %1; cvt.u32.u64 %0, t; }" : "=r"(a) : "l"(p));
    return a;
}
#define SWZ(off) ((off) ^ (((off) >> 3) & 0x70))

#define LDSM4(r, addr) \
    asm volatile("ldmatrix.sync.aligned.m8n8.x4.shared.b16 {%0,%1,%2,%3}, [%4];" \
                 : "=r"((r)[0]), "=r"((r)[1]), "=r"((r)[2]), "=r"((r)[3]) : "r"(addr))

static constexpr int ASZ_C = 128 * 128;   // 16KB: A tile (128 rows x 64 fp16)
static constexpr int BSZ_C = 256 * 128;   // 32KB: B tile (256 rows x 64 fp16)
static constexpr int STG1  = ASZ_C + BSZ_C;   // 48KB stage
static constexpr int SM1   = 4 * STG1;        // 196608 (4-stage single-pass)
static constexpr int STG3  = 2 * STG1;        // 96KB (recheck: 2 parts)
static constexpr int SM_CMB = 2 * STG3;       // 196608

// ---- 8 warps, warp grid 2(m) x 4(n), warp tile 64x64 ----
__device__ __forceinline__ void mmas(float (&acc)[4][8][4],
                                     uint32_t (&a)[4][4], uint32_t (&b)[4][4]) {
    #pragma unroll
    for (int ms = 0; ms < 4; ms++)
        #pragma unroll
        for (int ns = 0; ns < 8; ns++) {
            uint32_t b0 = b[ns >> 1][ns & 1];
            uint32_t b1 = b[ns >> 1][2 + (ns & 1)];
            asm volatile(
                "mma.sync.aligned.m16n8k16.row.col.f32.f16.f16.f32 "
                "{%0,%1,%2,%3}, {%4,%5,%6,%7}, {%8,%9}, {%0,%1,%2,%3};"
                : "+f"(acc[ms][ns][0]), "+f"(acc[ms][ns][1]),
                  "+f"(acc[ms][ns][2]), "+f"(acc[ms][ns][3])
                : "r"(a[ms][0]), "r"(a[ms][1]), "r"(a[ms][2]), "r"(a[ms][3]),
                  "r"(b0), "r"(b1));
        }
}

__device__ __forceinline__ void ldfrag(uint32_t Ab, uint32_t Bb, int wm, int wn,
                                       int r16, int kb,
                                       uint32_t (&a)[4][4], uint32_t (&b)[4][4]) {
    #pragma unroll
    for (int ms = 0; ms < 4; ms++)
        LDSM4(a[ms], Ab + SWZ((wm * 64 + ms * 16 + r16) * 128 + kb));
    #pragma unroll
    for (int nt = 0; nt < 4; nt++)
        LDSM4(b[nt], Bb + SWZ((wn * 64 + nt * 16 + r16) * 128 + kb));
}

__device__ __forceinline__ void compute_chunk1(uint32_t Ab, uint32_t Bb,
        float (&acc)[4][8][4], int wm, int wn, int lane) {
    const int r16 = lane & 15;
    const int kg  = (lane >> 4) * 16;
    #pragma unroll
    for (int ks = 0; ks < 4; ks++) {
        const int kb = ks * 32 + kg;
        uint32_t a[4][4], b[4][4];
        ldfrag(Ab, Bb, wm, wn, r16, kb, a, b);
        mmas(acc, a, b);
    }
}

// ---- loaders ----
__device__ __forceinline__ void load1(uint32_t dstbase, int kc, int m0, int n0,
                                      int tid, const __half* __restrict__ A0,
                                      const __half* __restrict__ B0) {
    for (int idx = tid; idx < 3072; idx += 256) {
        uint32_t dst;
        const __half* src;
        if (idx < 1024) {
            int r = idx >> 3, i = idx & 7;
            dst = dstbase + SWZ(r * 128 + i * 16);
            src = A0 + (size_t)(m0 + r) * H + kc * 64 + i * 8;
        } else {
            int j = idx - 1024;
            int r = j >> 3, i = j & 7;
            dst = dstbase + ASZ_C + SWZ(r * 128 + i * 16);
            src = B0 + (size_t)(n0 + r) * H + kc * 64 + i * 8;
        }
        asm volatile("cp.async.cg.shared.global [%0], [%1], 16;" :: "r"(dst), "l"(src) : "memory");
    }
    asm volatile("cp.async.commit_group;" ::: "memory");
}

__device__ __forceinline__ void load3(uint32_t dstbase, int kc, int tid,
                                      const int* rs, int n0,
                                      const __half* __restrict__ A0,
                                      const __half* __restrict__ A1,
                                      const __half* __restrict__ B0,
                                      const __half* __restrict__ B1) {
    for (int idx = tid; idx < 2048 + 4096; idx += 256) {
        uint32_t dst;
        const __half* src;
        if (idx < 2048) {
            int s = idx >> 10;
            int r = (idx & 1023) >> 3;
            int i = idx & 7;
            dst = dstbase + s * ASZ_C + SWZ(r * 128 + i * 16);
            src = (s ? A1 : A0) + (size_t)rs[r] * H + kc * 64 + i * 8;
        } else {
            int j = idx - 2048;
            int s = j >> 11;
            int r = (j & 2047) >> 3;
            int i = j & 7;
            dst = dstbase + 2 * ASZ_C + s * BSZ_C + SWZ(r * 128 + i * 16);
            src = (s ? B1 : B0) + (size_t)(n0 + r) * H + kc * 64 + i * 8;
        }
        asm volatile("cp.async.cg.shared.global [%0], [%1], 16;" :: "r"(dst), "l"(src) : "memory");
    }
    asm volatile("cp.async.commit_group;" ::: "memory");
}

// ---- single-pass GEMM body (compile-time C/EX), 256 threads ----
// 4-stage one-sync mainloop: wait -> sync -> issue load(c+3) -> compute(c).
// The sync proves all warps finished compute(c-1); buffer (c-1)%4 == (c+3)%4
// is exactly what the new load overwrites.
template <int C, bool EX>
__device__ __forceinline__ void gemm1_body(
    uint32_t base, int m0, int n0, int tid,
    const __half* __restrict__ A0, const __half* __restrict__ B0,
    const float* __restrict__ bias1, const float* __restrict__ W2,
    const float* __restrict__ W1o, float* __restrict__ accout,
    const float* __restrict__ tcv, const float* __restrict__ ccv,
    const float* __restrict__ tkv, int Ntot)
{
    constexpr int NC = H / 64;
    const int lane = tid & 31;
    const int wid  = tid >> 5;
    const int wm   = wid >> 2;
    const int wn   = wid & 3;

    float acc[4][8][4];
    #pragma unroll
    for (int a = 0; a < 4; a++)
        #pragma unroll
        for (int b = 0; b < 8; b++)
            #pragma unroll
            for (int c = 0; c < 4; c++) acc[a][b][c] = 0.f;

    load1(base + 0 * STG1, 0, m0, n0, tid, A0, B0);
    load1(base + 1 * STG1, 1, m0, n0, tid, A0, B0);
    load1(base + 2 * STG1, 2, m0, n0, tid, A0, B0);

    for (int c = 0; c < NC; c++) {
        if (c + 2 < NC)      asm volatile("cp.async.wait_group %0;" :: "n"(2) : "memory");
        else if (c + 1 < NC) asm volatile("cp.async.wait_group %0;" :: "n"(1) : "memory");
        else                 asm volatile("cp.async.wait_group %0;" :: "n"(0) : "memory");
        __syncthreads();
        if (c + 3 < NC)
            load1(base + ((c + 3) & 3) * STG1, c + 3, m0, n0, tid, A0, B0);
        const uint32_t sb = base + (c & 3) * STG1;
        compute_chunk1(sb, sb + ASZ_C, acc, wm, wn, lane);
    }

    float ccs = 0.f, tks = 0.f;
    if (EX) { ccs = ccv[m0 >> 12]; tks = tkv[m0 >> 12]; }

    #pragma unroll
    for (int ms = 0; ms < 4; ms++) {
        #pragma unroll
        for (int hh = 0; hh < 2; hh++) {
            const int r = m0 + wm * 64 + ms * 16 + (lane >> 2) + hh * 8;
            float tc = 0.f;
            if (EX) tc = tcv[r];
            float pc[C];
            #pragma unroll
            for (int ci = 0; ci < C; ci++) pc[ci] = 0.f;
            #pragma unroll
            for (int ns = 0; ns < 8; ns++) {
                #pragma unroll
                for (int e = 0; e < 2; e++) {
                    const int n = n0 + wn * 64 + ns * 8 + (lane & 3) * 2 + e;
                    float v = acc[ms][ns][hh * 2 + e] + bias1[n];
                    if (EX) {
                        v += tc  * W1o[(size_t)2048 * Ntot + n]
                           + ccs * W1o[(size_t)2049 * Ntot + n]
                           + tks * W1o[(size_t)2050 * Ntot + n];
                    }
                    float h = gelu_exact(v);
                    #pragma unroll
                    for (int ci = 0; ci < C; ci++)
                        pc[ci] = fmaf(h, W2[(size_t)n * C + ci], pc[ci]);
                }
            }
            #pragma unroll
            for (int ci = 0; ci < C; ci++) {
                pc[ci] += __shfl_xor_sync(0xffffffffu, pc[ci], 1);
                pc[ci] += __shfl_xor_sync(0xffffffffu, pc[ci], 2);
            }
            if ((lane & 3) == 0) {
                #pragma unroll
                for (int ci = 0; ci < C; ci++)
                    atomicAdd(&accout[(size_t)r * C + ci], pc[ci]);
            }
        }
    }
}

// ---- fused tok+eff GEMM: bid-dispatch, same compile-time body ----
__global__ void __launch_bounds__(256, 1)
tc_gemm_tokeff(const __half* __restrict__ X0,
               const __half* __restrict__ Wt0, const __half* __restrict__ We0,
               const float* __restrict__ tokb1, const float* __restrict__ tokW2,
               const float* __restrict__ effb1, const float* __restrict__ effW2,
               float* __restrict__ r0, float* __restrict__ r1)
{
    extern __shared__ char smem[];
    const int seg = blockIdx.x >> 2;
    const int n0  = (blockIdx.x & 3) * 256;
    gemm1_body<1, false>(smem_to_u32(smem), blockIdx.y * 128, n0, threadIdx.x,
                         X0, seg ? We0 : Wt0,
                         seg ? effb1 : tokb1, seg ? effW2 : tokW2,
                         nullptr, seg ? r1 : r0, nullptr, nullptr, nullptr, HH);
}

// ---- sup GEMM ----
template <int C, bool EX>
__global__ void __launch_bounds__(256, 1)
tc_gemm1(const __half* __restrict__ A0, const __half* __restrict__ B0,
         const float* __restrict__ bias1, const float* __restrict__ W2,
         const float* __restrict__ W1o, float* __restrict__ accout,
         const float* __restrict__ tcv, const float* __restrict__ ccv,
         const float* __restrict__ tkv, int Ntot)
{
    extern __shared__ char smem[];
    gemm1_body<C, EX>(smem_to_u32(smem), blockIdx.y * 128, blockIdx.x * 256,
                      threadIdx.x, A0, B0, bias1, W2, W1o, accout, tcv, ccv, tkv, Ntot);
}

// ---- gathered 3-term recheck body (unchanged, measured-good) ----
__device__ __forceinline__ void recheck_body(
    uint32_t base, int m0, int n0, int tid, int* rowsm,
    const __half* __restrict__ A0, const __half* __restrict__ A1,
    const __half* __restrict__ B0, const __half* __restrict__ B1,
    const float* __restrict__ bias1, const float* __restrict__ W2,
    const float* __restrict__ W1o, float* __restrict__ accout,
    const float* __restrict__ tcv, const float* __restrict__ ccv,
    const float* __restrict__ tkv)
{
    constexpr int NC = H / 64;
    const int lane = tid & 31;
    const int wid  = tid >> 5;
    const int wm   = wid >> 2;
    const int wn   = wid & 3;

    for (int i = tid; i < 128; i += 256) rowsm[i] = g_rowmap[m0 + i];
    __syncthreads();

    float acc[4][8][4];
    #pragma unroll
    for (int a = 0; a < 4; a++)
        #pragma unroll
        for (int b = 0; b < 8; b++)
            #pragma unroll
            for (int c = 0; c < 4; c++) acc[a][b][c] = 0.f;

    load3(base, 0, tid, rowsm, n0, A0, A1, B0, B1);

    for (int c = 0; c < NC; c++) {
        if (c + 1 < NC)
            load3(base + ((c + 1) & 1) * STG3, c + 1, tid, rowsm, n0, A0, A1, B0, B1);
        if (c + 1 < NC) asm volatile("cp.async.wait_group %0;" :: "n"(1) : "memory");
        else            asm volatile("cp.async.wait_group %0;" :: "n"(0) : "memory");
        __syncthreads();
        const uint32_t sb = base + (c & 1) * STG3;
        const uint32_t Ab = sb, Bb = sb + 2 * ASZ_C;
        {
            const int r16 = lane & 15;
            const int kg  = (lane >> 4) * 16;
            #pragma unroll
            for (int ks = 0; ks < 4; ks++) {
                const int kb = ks * 32 + kg;
                uint32_t af0[4][4], bf0[4][4];
                #pragma unroll
                for (int ms = 0; ms < 4; ms++)
                    LDSM4(af0[ms], Ab + SWZ((wm * 64 + ms * 16 + r16) * 128 + kb));
                #pragma unroll
                for (int nt = 0; nt < 4; nt++)
                    LDSM4(bf0[nt], Bb + SWZ((wn * 64 + nt * 16 + r16) * 128 + kb));
                mmas(acc, af0, bf0);
                uint32_t af1[4][4];
                #pragma unroll
                for (int ms = 0; ms < 4; ms++)
                    LDSM4(af1[ms], Ab + ASZ_C + SWZ((wm * 64 + ms * 16 + r16) * 128 + kb));
                mmas(acc, af1, bf0);
                uint32_t bf1[4][4];
                #pragma unroll
                for (int nt = 0; nt < 4; nt++)
                    LDSM4(bf1[nt], Bb + BSZ_C + SWZ((wn * 64 + nt * 16 + r16) * 128 + kb));
                mmas(acc, af0, bf1);
            }
        }
        __syncthreads();
    }

    #pragma unroll
    for (int ms = 0; ms < 4; ms++) {
        #pragma unroll
        for (int hh = 0; hh < 2; hh++) {
            const int slot = m0 + wm * 64 + ms * 16 + (lane >> 2) + hh * 8;
            const int rg   = rowsm[slot - m0];
            float tc = tcv[rg], ccs = ccv[rg >> 12], tks = tkv[rg >> 12];
            float pc[SUPC];
            #pragma unroll
            for (int ci = 0; ci < SUPC; ci++) pc[ci] = 0.f;
            #pragma unroll
            for (int ns = 0; ns < 8; ns++) {
                #pragma unroll
                for (int e = 0; e < 2; e++) {
                    const int n = n0 + wn * 64 + ns * 8 + (lane & 3) * 2 + e;
                    float v = acc[ms][ns][hh * 2 + e] + bias1[n];
                    v += tc  * W1o[(size_t)2048 * H + n]
                       + ccs * W1o[(size_t)2049 * H + n]
                       + tks * W1o[(size_t)2050 * H + n];
                    float h = gelu_exact(v);
                    #pragma unroll
                    for (int ci = 0; ci < SUPC; ci++)
                        pc[ci] = fmaf(h, W2[(size_t)n * SUPC + ci], pc[ci]);
                }
            }
            #pragma unroll
            for (int ci = 0; ci < SUPC; ci++) {
                pc[ci] += __shfl_xor_sync(0xffffffffu, pc[ci], 1);
                pc[ci] += __shfl_xor_sync(0xffffffffu, pc[ci], 2);
            }
            if ((lane & 3) == 0) {
                #pragma unroll
                for (int ci = 0; ci < SUPC; ci++)
                    atomicAdd(&accout[(size_t)slot * SUPC + ci], pc[ci]);
            }
        }
    }
}

// ---- combined dep GEMM + recheck (single launch -> overlap) ----
__global__ void __launch_bounds__(256, 1)
tc_gemm_dep_re(const __half* __restrict__ X0, const __half* __restrict__ X1,
               const __half* __restrict__ Wd0,
               const __half* __restrict__ Ws0, const __half* __restrict__ Ws1,
               const float* __restrict__ depb1, const float* __restrict__ depW2,
               const float* __restrict__ depW1,
               const float* __restrict__ supb1, const float* __restrict__ supW2,
               const float* __restrict__ supW1,
               float* __restrict__ dlog, float* __restrict__ rlog,
               const float* __restrict__ tcv, const float* __restrict__ ccv,
               const float* __restrict__ tkv)
{
    extern __shared__ char smem[];
    __shared__ int rowsm[128];
    const uint32_t base = smem_to_u32(smem);
    const int bid = blockIdx.x;
    const int tid = threadIdx.x;

    if (bid < RE_BLOCKS) {
        const int m0 = (bid >> 3) * 128;
        const int n0 = (bid & 7) * 256;
        if (m0 >= g_count) return;
        recheck_body(base, m0, n0, tid, rowsm, X0, X1, Ws0, Ws1,
                     supb1, supW2, supW1, rlog, tcv, ccv, tkv);
    } else {
        const int b2 = bid - RE_BLOCKS;
        const int m0 = (b2 >> 3) * 128;
        const int n0 = (b2 & 7) * 256;
        // dep uses 2-stage window of the 4-stage smem (fits: needs 3*STG1 max)
        gemm1_body<HEADSC, true>(base, m0, n0, tid, X0, Wd0,
                                 depb1, depW2, depW1, dlog, tcv, ccv, tkv, H);
    }
}

// ================= precompute: fused prep (transpose jobs + X split/mean) ====
// grid (64, 64, 5): z=0..3 transpose jobs; z=4 X split+mean (uses x as block id)
__global__ void prep_all(const float* __restrict__ X,
                         const float* __restrict__ tokW1,
                         const float* __restrict__ effW1,
                         const float* __restrict__ supW1,
                         const float* __restrict__ depW1,
                         __half* __restrict__ o_tok, __half* __restrict__ o_eff,
                         __half* __restrict__ o_sup0, __half* __restrict__ o_sup1,
                         __half* __restrict__ o_dep)
{
    __shared__ float t[32][33];
    const int job = blockIdx.z;

    if (job == 4) {
        // X split (hi) + column mean partials: 64x8=512 virtual blocks
        const int vb  = blockIdx.y * 64 + blockIdx.x;   // 0..4095, use first 512
        if (vb >= 512) return;
        int idx = vb * 256 + threadIdx.x;
        int d     = idx & (H - 1);
        int chunk = (idx >> 11) & 15;
        int b     = idx >> 15;
        size_t p = ((size_t)(b * SEQ + chunk * 256)) * H + d;
        float s = 0.f;
        #pragma unroll 4
        for (int tt = 0; tt < 256; tt++) {
            float x = X[p];
            s += x;
            gX0[p] = __float2half_rn(x);
            p += H;
        }
        atomicAdd(&g_ctxsum[b * H + d], s);
        return;
    }

    const float* W; int N; int nsplit; __half *o0, *o1;
    if      (job == 0) { W = tokW1; N = HH; nsplit = 1; o0 = o_tok;  o1 = o_tok;  }
    else if (job == 1) { W = effW1; N = HH; nsplit = 1; o0 = o_eff;  o1 = o_eff;  }
    else if (job == 2) { W = supW1; N = H;  nsplit = 2; o0 = o_sup0; o1 = o_sup1; }
    else               { W = depW1; N = H;  nsplit = 1; o0 = o_dep;  o1 = o_dep;  }

    int n0 = blockIdx.x * 32, k0 = blockIdx.y * 32;
    if (n0 >= N) return;
    int tx = threadIdx.x & 31, ty = threadIdx.x >> 5;
    #pragma unroll
    for (int s = 0; s < 32; s += 8)
        t[ty + s][tx] = W[(size_t)(k0 + ty + s) * N + n0 + tx];
    __syncthreads();
    #pragma unroll
    for (int s = 0; s < 32; s += 8) {
        int n = n0 + ty + s, k = k0 + tx;
        float x = t[tx][ty + s];
        __half hh = __float2half_rn(x);
        o0[(size_t)n * H + k] = hh;
        if (nsplit == 2) {
            float r = x - __half2float(hh);
            o1[(size_t)n * H + k] = __float2half_rn(r);
        }
    }
}

// lazy residual split: only for flagged rows (grid RE_MAX_ROWS, early exit)
__global__ void fill_x1_flagged(const float* __restrict__ X) {
    const int slot = blockIdx.x;
    if (slot >= g_count || slot >= RE_MAX_ROWS) return;
    const int row = g_rowmap[slot];
    const int tid = threadIdx.x;   // 256 threads, 8 elems each
    #pragma unroll
    for (int i = 0; i < 8; i++) {
        size_t p = (size_t)row * H + tid * 8 + i;
        float x = X[p];
        __half h = __float2half_rn(x);
        gX1[p] = __float2half_rn(x - __half2float(h));
    }
}

__global__ void zero_scratch() {
    int i = blockIdx.x * blockDim.x + threadIdx.x;
    if (i == 0)               g_count = 0;
    if (i < BATCH * H)        g_ctxsum[i] = 0.f;
    if (i < 8 * HH)           (&g_hid[0][0])[i] = 0.f;
    if (i < M_ROWS)         { g_rowsum0[i] = 0.f; g_rowsum1[i] = 0.f; g_rowmap[i] = 0; }
    if (i < M_ROWS * SUPC)  { g_slog[i] = 0.f; g_rlog[i] = 0.f; }
    if (i < M_ROWS * HEADSC)  g_dlog[i] = 0.f;
}

// ---- ctx/task MLP, chip-wide: partial k-chunks then finalize ----
__global__ void ctx_task_partial(
    const float* __restrict__ cW1, const float* __restrict__ tW1)
{
    __shared__ float embs[64];
    const int k0  = blockIdx.x * 64;
    const int job = blockIdx.y;
    const int b     = job & 3;
    const int which = job >> 2;
    const float* W1 = which ? tW1 : cW1;
    const int tid = threadIdx.x;

    if (tid < 64) embs[tid] = g_ctxsum[b * H + k0 + tid] * (1.0f / SEQ);
    __syncthreads();

    float p = 0.f;
    #pragma unroll
    for (int kk = 0; kk < 64; kk++)
        p = fmaf(embs[kk], W1[(size_t)(k0 + kk) * HH + tid], p);
    atomicAdd(&g_hid[job][tid], p);
}

__global__ void ctx_task_final(
    const float* __restrict__ cb1, const float* __restrict__ cW2,
    const float* __restrict__ cb2,
    const float* __restrict__ tb1, const float* __restrict__ tW2,
    const float* __restrict__ tb2,
    float* __restrict__ out)
{
    __shared__ float red[1024];
    const int job = blockIdx.x;
    const int b     = job & 3;
    const int which = job >> 2;
    const float* b1 = which ? tb1 : cb1;
    const float* W2 = which ? tW2 : cW2;
    const float* b2 = which ? tb2 : cb2;
    const int tid = threadIdx.x;

    float a = g_hid[job][tid] + b1[tid];
    red[tid] = gelu_exact(a) * W2[tid];
    __syncthreads();
    for (int off = 512; off > 0; off >>= 1) {
        if (tid < off) red[tid] += red[tid + off];
        __syncthreads();
    }
    if (tid == 0)
        out[(which ? OFF_TASK : OFF_CTX) + b] = sigmoidf_(red[0] + b2[0]);
}

// ================= small finalize kernels =================
__global__ void finalize_tokeff(float* __restrict__ out,
                                const float* __restrict__ tokb2,
                                const float* __restrict__ effb2)
{
    int r = blockIdx.x * blockDim.x + threadIdx.x;
    if (r < M_ROWS) {
        out[OFF_TOK + r] = sigmoidf_(g_rowsum0[r] + tokb2[0]);
        out[OFF_EFF + r] = sigmoidf_(g_rowsum1[r] + effb2[0]);
    }
}

__global__ void softmax_sup_flag(float* __restrict__ out,
                                 const float* __restrict__ supb2)
{
    int r = blockIdx.x * blockDim.x + threadIdx.x;
    if (r >= M_ROWS) return;
    float l[SUPC];
    float m = -1e30f;
    #pragma unroll
    for (int c = 0; c < SUPC; c++) {
        l[c] = g_slog[(size_t)r * SUPC + c] + supb2[c];
        m = fmaxf(m, l[c]);
    }
    float s = 0.f;
    #pragma unroll
    for (int c = 0; c < SUPC; c++) { l[c] = expf(l[c] - m); s += l[c]; }
    float inv = 1.f / s;
    float eff = out[OFF_EFF + r];
    bool flag = false;
    #pragma unroll
    for (int c = 0; c < SUPC; c++) {
        float w = l[c] * inv;
        if (fabsf(w - 0.2f) < RECHECK_MARGIN) flag = true;
        out[OFF_SUP  + (size_t)r * SUPC + c] = w;
        out[OFF_MASK + (size_t)r * SUPC + c] = (w > 0.2f) ? eff : 0.f;
    }
    if (flag) {
        int slot = atomicAdd(&g_count, 1);
        if (slot < M_ROWS) g_rowmap[slot] = r;
    }
}

__global__ void softmax_dep_refinal(float* __restrict__ out,
                                    const float* __restrict__ depb2,
                                    const float* __restrict__ supb2)
{
    int r = blockIdx.x * blockDim.x + threadIdx.x;
    if (r >= M_ROWS) return;
    {
        float l[HEADSC];
        float m = -1e30f;
        #pragma unroll
        for (int c = 0; c < HEADSC; c++) {
            l[c] = g_dlog[(size_t)r * HEADSC + c] + depb2[c];
            m = fmaxf(m, l[c]);
        }
        float s = 0.f;
        #pragma unroll
        for (int c = 0; c < HEADSC; c++) { l[c] = expf(l[c] - m); s += l[c]; }
        float inv = 1.f / s;
        #pragma unroll
        for (int c = 0; c < HEADSC; c++)
            out[OFF_DEP + (size_t)r * HEADSC + c] = l[c] * inv;
    }
    int t = r;
    if (t < g_count && t < RE_MAX_ROWS) {
        int rr = g_rowmap[t];
        float l[SUPC];
        float m = -1e30f;
        #pragma unroll
        for (int c = 0; c < SUPC; c++) {
            l[c] = g_rlog[(size_t)t * SUPC + c] + supb2[c];
            m = fmaxf(m, l[c]);
        }
        float s = 0.f;
        #pragma unroll
        for (int c = 0; c < SUPC; c++) { l[c] = expf(l[c] - m); s += l[c]; }
        float inv = 1.f / s;
        float eff = out[OFF_EFF + rr];
        #pragma unroll
        for (int c = 0; c < SUPC; c++) {
            float w = l[c] * inv;
            out[OFF_SUP  + (size_t)rr * SUPC + c] = w;
            out[OFF_MASK + (size_t)rr * SUPC + c] = (w > 0.2f) ? eff : 0.f;
        }
    }
}

// ================= launch =================
extern "C" void kernel_launch(void* const* d_in, const int* in_sizes, int n_in,
                              void* d_out, int out_size)
{
    const float* X      = (const float*)d_in[0];
    const float* tokW1  = (const float*)d_in[1];
    const float* tokb1  = (const float*)d_in[2];
    const float* tokW2  = (const float*)d_in[3];
    const float* tokb2  = (const float*)d_in[4];
    const float* ctxW1  = (const float*)d_in[5];
    const float* ctxb1  = (const float*)d_in[6];
    const float* ctxW2  = (const float*)d_in[7];
    const float* ctxb2  = (const float*)d_in[8];
    const float* taskW1 = (const float*)d_in[9];
    const float* taskb1 = (const float*)d_in[10];
    const float* taskW2 = (const float*)d_in[11];
    const float* taskb2 = (const float*)d_in[12];
    const float* effW1  = (const float*)d_in[13];
    const float* effb1  = (const float*)d_in[14];
    const float* effW2  = (const float*)d_in[15];
    const float* effb2  = (const float*)d_in[16];
    const float* supW1  = (const float*)d_in[17];
    const float* supb1  = (const float*)d_in[18];
    const float* supW2  = (const float*)d_in[19];
    const float* supb2  = (const float*)d_in[20];
    const float* depW1  = (const float*)d_in[21];
    const float* depb1  = (const float*)d_in[22];
    const float* depW2  = (const float*)d_in[23];
    const float* depb2  = (const float*)d_in[24];
    float* out = (float*)d_out;

    void *pX0, *pX1, *pWt0, *pWe0, *pWs0, *pWs1, *pWd0;
    void *pR0, *pR1, *pSL, *pDL, *pRL;
    cudaGetSymbolAddress(&pX0, gX0);   cudaGetSymbolAddress(&pX1, gX1);
    cudaGetSymbolAddress(&pWt0, gWtok0);
    cudaGetSymbolAddress(&pWe0, gWeff0);
    cudaGetSymbolAddress(&pWs0, gWsup0); cudaGetSymbolAddress(&pWs1, gWsup1);
    cudaGetSymbolAddress(&pWd0, gWdep0);
    cudaGetSymbolAddress(&pR0, g_rowsum0); cudaGetSymbolAddress(&pR1, g_rowsum1);
    cudaGetSymbolAddress(&pSL, g_slog);    cudaGetSymbolAddress(&pDL, g_dlog);
    cudaGetSymbolAddress(&pRL, g_rlog);

    cudaFuncSetAttribute(tc_gemm_tokeff,
                         cudaFuncAttributeMaxDynamicSharedMemorySize, SM1);
    cudaFuncSetAttribute(tc_gemm1<SUPC, true>,
                         cudaFuncAttributeMaxDynamicSharedMemorySize, SM1);
    cudaFuncSetAttribute(tc_gemm_dep_re,
                         cudaFuncAttributeMaxDynamicSharedMemorySize, SM_CMB);

    zero_scratch<<<512, 256>>>();
    // fused prep: 4 transpose jobs + X split/mean in one launch
    prep_all<<<dim3(64, 64, 5), 256>>>(
        X, tokW1, effW1, supW1, depW1,
        (__half*)pWt0, (__half*)pWe0, (__half*)pWs0, (__half*)pWs1, (__half*)pWd0);

    // ctx/task MLP: chip-wide partials + tiny finalize
    ctx_task_partial<<<dim3(H / 64, 8), 1024>>>(ctxW1, taskW1);
    ctx_task_final<<<8, 1024>>>(ctxb1, ctxW2, ctxb2, taskb1, taskW2, taskb2, out);

    // fused tok + eff GEMM
    tc_gemm_tokeff<<<dim3(8, M_ROWS / 128), 256, SM1>>>(
        (const __half*)pX0, (const __half*)pWt0, (const __half*)pWe0,
        tokb1, tokW2, effb1, effW2, (float*)pR0, (float*)pR1);
    finalize_tokeff<<<M_ROWS / 256, 256>>>(out, tokb2, effb2);

    // sup: single-pass fp16 with extra features
    tc_gemm1<SUPC, true><<<dim3(H / 256, M_ROWS / 128), 256, SM1>>>(
        (const __half*)pX0, (const __half*)pWs0,
        supb1, supW2, supW1, (float*)pSL,
        out + OFF_TOK, out + OFF_CTX, out + OFF_TASK, H);

    softmax_sup_flag<<<M_ROWS / 256, 256>>>(out, supb2);

    // lazy residual split for flagged rows only
    fill_x1_flagged<<<RE_MAX_ROWS, 256>>>(X);

    // combined: recheck blocks (first wave) + dep GEMM blocks — overlapped
    tc_gemm_dep_re<<<RE_BLOCKS + 8 * (M_ROWS / 128), 256, SM_CMB>>>(
        (const __half*)pX0, (const __half*)pX1, (const __half*)pWd0,
        (const __half*)pWs0, (const __half*)pWs1,
        depb1, depW2, depW1, supb1, supW2, supW1,
        (float*)pDL, (float*)pRL,
        out + OFF_TOK, out + OFF_CTX, out + OFF_TASK);

    softmax_dep_refinal<<<M_ROWS / 256, 256>>>(out, depb2, supb2);

    (void)in_sizes; (void)n_in; (void)out_size;
}